// round 11
// baseline (speedup 1.0000x reference)
#include <cuda_runtime.h>
#include <math.h>

#define B_    128
#define PAST_ 256
#define FUT_  128
#define D_    128
#define RU_   512
#define LD_   128
#define FCN_  512
#define TL_   128
#define HDEC_ 640
#define G3RU  1536
#define G3HD  1920
#define MAXBLK 2048

// ---------------- static device scratch (no allocations anywhere) ----------
__device__ float g_gi_phi[(size_t)B_ * PAST_ * G3RU];      // 201 MB
__device__ float g_gi_xr [(size_t)B_ * FUT_  * G3RU];      // 100 MB
__device__ float g_h_phi [B_ * RU_];
__device__ float g_h_xr  [B_ * RU_];
__device__ float g_feat  [B_ * 2 * RU_];
__device__ float g_ghp   [(size_t)2 * 8 * B_ * G3RU];      // enc gh partials [g][s<8]
__device__ float g_m1p   [(size_t)2 * 16 * B_ * 512];
__device__ float g_m2p   [2 * 8 * B_ * 256];
__device__ float g_m3p   [2 * 4 * B_ * 128];
__device__ float g_hdec  [B_ * HDEC_];
__device__ float g_xdec  [B_ * D_];
__device__ float g_dghp  [(size_t)12 * B_ * G3HD];         // dec: s=0..1 Gi, s=2..11 Gh
__device__ float g_fcp   [(size_t)20 * B_ * FCN_];
__device__ float g_outp  [16 * B_ * D_];
__device__ unsigned g_slots[MAXBLK];

// ---------------- polite lock-free grid barrier ----------------------------
__device__ __forceinline__ void gridbar(unsigned &gen) {
    gen++;
    __syncthreads();
    __threadfence();
    if (threadIdx.x == 0) *(volatile unsigned*)&g_slots[blockIdx.x] = gen;
    if (threadIdx.x < 32) {
        const int nb = gridDim.x;
        unsigned delay = 32;
        for (;;) {
            bool done = true;
            for (int s = threadIdx.x; s < nb; s += 32)
                if (*(volatile unsigned*)&g_slots[s] < gen) done = false;
            if (__all_sync(0xffffffffu, done)) break;
            __nanosleep(delay);
            if (delay < 1024) delay <<= 1;
        }
        __threadfence();
    }
    __syncthreads();
}

__device__ __forceinline__ float actf(float v, int act) {
    if (act == 1) return v > 0.f ? v : 0.01f * v;   // leaky_relu
    if (act == 2) return fmaxf(v, 0.f);             // relu
    return v;
}
__device__ __forceinline__ float sigm(float x) { return 1.f / (1.f + expf(-x)); }

__device__ __forceinline__ float4 ld4cg(const float* p) { return __ldcg((const float4*)p); }
__device__ __forceinline__ float4 ld4g (const float* p) { return __ldg ((const float4*)p); }
__device__ __forceinline__ void st4cg(float* p, float4 v) { __stcg((float4*)p, v); }

// packed f32x2 FMA (FFMA2): two fp32 fmaf per instruction, RN rounding each half
__device__ __forceinline__ unsigned long long ffma2(
    unsigned long long a, unsigned long long b, unsigned long long c)
{
    unsigned long long d;
    asm("fma.rn.f32x2 %0, %1, %2, %3;" : "=l"(d) : "l"(a), "l"(b), "l"(c));
    return d;
}
__device__ __forceinline__ float2 unpk(unsigned long long u) {
    float2 f;
    asm("mov.b64 {%0, %1}, %2;" : "=f"(f.x), "=f"(f.y) : "l"(u));
    return f;
}

// ---------------- 64x64 tile GEMM, 64 threads, 8x8/thread, f32x2 -----------
// C[m0..+64, n0..+64] = A[:, k0..+32*nchunk] @ W[:, ...]^T (+bias if addBias)
// A-loader optionally reduces nred partials (stride pstride, activation actIn)
// and, if aux != null, writes the reduced (pre-activation) A values to aux.
struct Smem2 {
    float2 AsD[32][64];    // duplicated pairs (a,a): 16 KB
    float  Ws [32][68];    // 8.5 KB (pad keeps float4 alignment)
};

__device__ __noinline__ void tile64(
    Smem2* sm,
    const float* __restrict__ A, int ldA, size_t pstride, int nred, int actIn,
    const float* __restrict__ W, int ldW,
    const float* __restrict__ bias, int addBias,
    float* __restrict__ C, int ldC,
    float* __restrict__ aux, int auxLd,
    int m0, int n0, int k0, int nchunk)
{
    const int tid = threadIdx.x;          // 0..63
    const int tx8 = (tid & 7) * 8;        // col group
    const int ty8 = (tid >> 3) * 8;       // row group

    unsigned long long acc[8][4];
#pragma unroll
    for (int i = 0; i < 8; i++)
#pragma unroll
        for (int j = 0; j < 4; j++) acc[i][j] = 0ull;

#pragma unroll 1
    for (int ch = 0; ch < nchunk; ch++) {
        const int kb = k0 + ch * 32;
        // stage chunk: thread t owns A row m0+t and W row n0+t (32 k each)
        {
            const float* ap = A + (size_t)(m0 + tid) * ldA + kb;
            const float* wp = W + (size_t)(n0 + tid) * ldW + kb;
#pragma unroll
            for (int c4 = 0; c4 < 32; c4 += 4) {
                float4 v = ld4cg(ap + c4);
                if (nred > 1) {
                    for (int q = 1; q < nred; q++) {
                        float4 u = ld4cg(ap + (size_t)q * pstride + c4);
                        v.x += u.x; v.y += u.y; v.z += u.z; v.w += u.w;
                    }
                }
                if (aux) st4cg(aux + (size_t)(m0 + tid) * auxLd + kb + c4, v);
                sm->AsD[c4 + 0][tid] = make_float2(actf(v.x, actIn), actf(v.x, actIn));
                sm->AsD[c4 + 1][tid] = make_float2(actf(v.y, actIn), actf(v.y, actIn));
                sm->AsD[c4 + 2][tid] = make_float2(actf(v.z, actIn), actf(v.z, actIn));
                sm->AsD[c4 + 3][tid] = make_float2(actf(v.w, actIn), actf(v.w, actIn));
                float4 w = ld4g(wp + c4);
                sm->Ws[c4 + 0][tid] = w.x;
                sm->Ws[c4 + 1][tid] = w.y;
                sm->Ws[c4 + 2][tid] = w.z;
                sm->Ws[c4 + 3][tid] = w.w;
            }
        }
        __syncthreads();
#pragma unroll 8
        for (int kk = 0; kk < 32; kk++) {
            const longlong2 A01 = *(const longlong2*)&sm->AsD[kk][ty8 + 0];
            const longlong2 A23 = *(const longlong2*)&sm->AsD[kk][ty8 + 2];
            const longlong2 A45 = *(const longlong2*)&sm->AsD[kk][ty8 + 4];
            const longlong2 A67 = *(const longlong2*)&sm->AsD[kk][ty8 + 6];
            const longlong2 W03 = *(const longlong2*)&sm->Ws[kk][tx8];
            const longlong2 W47 = *(const longlong2*)&sm->Ws[kk][tx8 + 4];
            const unsigned long long w0 = (unsigned long long)W03.x;
            const unsigned long long w1 = (unsigned long long)W03.y;
            const unsigned long long w2 = (unsigned long long)W47.x;
            const unsigned long long w3 = (unsigned long long)W47.y;
            const unsigned long long a[8] = {
                (unsigned long long)A01.x, (unsigned long long)A01.y,
                (unsigned long long)A23.x, (unsigned long long)A23.y,
                (unsigned long long)A45.x, (unsigned long long)A45.y,
                (unsigned long long)A67.x, (unsigned long long)A67.y };
#pragma unroll
            for (int i = 0; i < 8; i++) {
                acc[i][0] = ffma2(a[i], w0, acc[i][0]);
                acc[i][1] = ffma2(a[i], w1, acc[i][1]);
                acc[i][2] = ffma2(a[i], w2, acc[i][2]);
                acc[i][3] = ffma2(a[i], w3, acc[i][3]);
            }
        }
        __syncthreads();
    }

    float4 b0 = make_float4(0.f, 0.f, 0.f, 0.f), b1 = b0;
    if (addBias) { b0 = ld4g(bias + n0 + tx8); b1 = ld4g(bias + n0 + tx8 + 4); }
#pragma unroll
    for (int i = 0; i < 8; i++) {
        const int m = m0 + ty8 + i;
        float2 p0 = unpk(acc[i][0]), p1 = unpk(acc[i][1]);
        float2 p2 = unpk(acc[i][2]), p3 = unpk(acc[i][3]);
        float4 v0 = make_float4(p0.x + b0.x, p0.y + b0.y, p1.x + b0.z, p1.y + b0.w);
        float4 v1 = make_float4(p2.x + b1.x, p2.y + b1.y, p3.x + b1.z, p3.y + b1.w);
        st4cg(C + (size_t)m * ldC + n0 + tx8, v0);
        st4cg(C + (size_t)m * ldC + n0 + tx8 + 4, v1);
    }
}

// ---------------- persistent kernel ---------------------------------------
__global__ void __launch_bounds__(64, 8) vae_persistent(
    const float* __restrict__ past, const float* __restrict__ future,
    const float* __restrict__ eps,
    const float* __restrict__ phi_Wih, const float* __restrict__ phi_Whh,
    const float* __restrict__ phi_bih, const float* __restrict__ phi_bhh,
    const float* __restrict__ xr_Wih,  const float* __restrict__ xr_Whh,
    const float* __restrict__ xr_bih,  const float* __restrict__ xr_bhh,
    const float* __restrict__ mu_W1, const float* __restrict__ mu_b1,
    const float* __restrict__ mu_W2, const float* __restrict__ mu_b2,
    const float* __restrict__ mu_W3, const float* __restrict__ mu_b3,
    const float* __restrict__ lv_W1, const float* __restrict__ lv_b1,
    const float* __restrict__ lv_W2, const float* __restrict__ lv_b2,
    const float* __restrict__ lv_W3, const float* __restrict__ lv_b3,
    const float* __restrict__ dec_Wih, const float* __restrict__ dec_Whh,
    const float* __restrict__ dec_bih, const float* __restrict__ dec_bhh,
    const float* __restrict__ fc_W, const float* __restrict__ fc_b,
    const float* __restrict__ out_W, const float* __restrict__ out_b,
    float* __restrict__ x_mu, float* __restrict__ z_mu_o, float* __restrict__ z_lv_o)
{
    __shared__ Smem2 sm;
    const int nblk = gridDim.x;
    const int bid  = blockIdx.x;
    const int tid  = threadIdx.x;
    const int gtid = bid * 64 + tid;
    const int nthr = nblk * 64;

    unsigned gen = *(volatile unsigned*)&g_slots[bid];

    // ---------- P0: time-parallel input projections + zero hidden ----------
    {
        const int T1 = (B_ * PAST_ / 64) * (G3RU / 64);   // 512*24 = 12288
        const int T2 = (B_ * FUT_  / 64) * (G3RU / 64);   // 256*24 = 6144
#pragma unroll 1
        for (int tl = bid; tl < T1 + T2; tl += nblk) {
            if (tl < T1) {
                int m0 = (tl / 24) * 64, n0 = (tl % 24) * 64;
                tile64(&sm, past, D_, 0, 1, 0, phi_Wih, D_, phi_bih, 1,
                       g_gi_phi, G3RU, 0, 0, m0, n0, 0, 4);
            } else {
                int r = tl - T1;
                int m0 = (r / 24) * 64, n0 = (r % 24) * 64;
                tile64(&sm, future, D_, 0, 1, 0, xr_Wih, D_, xr_bih, 1,
                       g_gi_xr, G3RU, 0, 0, m0, n0, 0, 4);
            }
        }
        for (int i = gtid; i < 2 * B_ * RU_ / 4; i += nthr) {
            float4 z = make_float4(0.f, 0.f, 0.f, 0.f);
            if (i < B_ * RU_ / 4) st4cg(&g_h_phi[i * 4], z);
            else                  st4cg(&g_h_xr[(i - B_ * RU_ / 4) * 4], z);
        }
    }
    gridbar(gen);

    // ---------- encoder recurrences ----------
#pragma unroll 1
    for (int t = 0; t < PAST_; t++) {
        const int ngru = (t < FUT_) ? 2 : 1;
        const int TT = 2 * 24 * 8;   // m x n x ksplit = 384 per GRU
#pragma unroll 1
        for (int tl = bid; tl < ngru * TT; tl += nblk) {
            int g = tl / TT, r = tl % TT;
            int s = r & 7; r >>= 3;                    // 8 K-slices of 64 (nchunk=2)
            int n0 = (r % 24) * 64, m0 = (r / 24) * 64;
            const float* A  = g ? g_h_xr : g_h_phi;
            const float* W  = g ? xr_Whh : phi_Whh;
            const float* bb = g ? xr_bhh : phi_bhh;
            float* C = g_ghp + ((size_t)g * 8 + s) * ((size_t)B_ * G3RU);
            tile64(&sm, A, RU_, 0, 1, 0, W, RU_, bb, s == 0, C, G3RU, 0, 0, m0, n0, s * 64, 2);
        }
        gridbar(gen);
        // GRU pointwise, float4, reduce 8 slices
        const int Q = RU_ / 4;   // 128
        for (int i = gtid; i < ngru * B_ * Q; i += nthr) {
            int g = i / (B_ * Q), r = i % (B_ * Q);
            int m = r / Q, j = (r % Q) * 4;
            float4 sr = make_float4(0.f,0.f,0.f,0.f), sz = sr, sn = sr;
#pragma unroll
            for (int s = 0; s < 8; s++) {
                const float* gp = g_ghp + ((size_t)g * 8 + s) * ((size_t)B_ * G3RU) + (size_t)m * G3RU;
                float4 a = ld4cg(gp + j);
                float4 b = ld4cg(gp + RU_ + j);
                float4 c = ld4cg(gp + 2 * RU_ + j);
                sr.x+=a.x; sr.y+=a.y; sr.z+=a.z; sr.w+=a.w;
                sz.x+=b.x; sz.y+=b.y; sz.z+=b.z; sz.w+=b.w;
                sn.x+=c.x; sn.y+=c.y; sn.z+=c.z; sn.w+=c.w;
            }
            const float* gim = g ? (g_gi_xr  + ((size_t)m * FUT_  + t) * G3RU)
                                 : (g_gi_phi + ((size_t)m * PAST_ + t) * G3RU);
            float4 ir = ld4cg(gim + j), iz = ld4cg(gim + RU_ + j), in = ld4cg(gim + 2 * RU_ + j);
            float* hp = (g ? g_h_xr : g_h_phi) + (size_t)m * RU_ + j;
            float4 hv = ld4cg(hp);
            float4 o;
            { float rr = sigm(ir.x + sr.x), zz = sigm(iz.x + sz.x);
              float nn = tanhf(in.x + rr * sn.x); o.x = (1.f - zz) * nn + zz * hv.x; }
            { float rr = sigm(ir.y + sr.y), zz = sigm(iz.y + sz.y);
              float nn = tanhf(in.y + rr * sn.y); o.y = (1.f - zz) * nn + zz * hv.y; }
            { float rr = sigm(ir.z + sr.z), zz = sigm(iz.z + sz.z);
              float nn = tanhf(in.z + rr * sn.z); o.z = (1.f - zz) * nn + zz * hv.z; }
            { float rr = sigm(ir.w + sr.w), zz = sigm(iz.w + sz.w);
              float nn = tanhf(in.w + rr * sn.w); o.w = (1.f - zz) * nn + zz * hv.w; }
            st4cg(hp, o);
        }
        gridbar(gen);
    }

    // ---------- features ----------
    for (int i = gtid; i < B_ * 2 * RU_ / 4; i += nthr) {
        int m = i / (2 * RU_ / 4), c = (i % (2 * RU_ / 4)) * 4;
        float4 v = (c < RU_) ? ld4cg(&g_h_phi[m * RU_ + c]) : ld4cg(&g_h_xr[m * RU_ + c - RU_]);
        st4cg(&g_feat[m * 2 * RU_ + c], v);
    }
    gridbar(gen);

    // ---------- MLP L1: [B,512], K=1024 (16 slices of 64, nchunk=2) --------
#pragma unroll 1
    for (int tl = bid; tl < 2 * 2 * 8 * 16; tl += nblk) {
        int br = tl / 256, r = tl % 256;
        int s = r & 15; r >>= 4;
        int n0 = (r % 8) * 64, m0 = (r / 8) * 64;
        const float* W = br ? lv_W1 : mu_W1;
        const float* bb = br ? lv_b1 : mu_b1;
        float* C = g_m1p + ((size_t)br * 16 + s) * (B_ * 512);
        tile64(&sm, g_feat, 2 * RU_, 0, 1, 0, W, 2 * RU_, bb, s == 0, C, 512, 0, 0, m0, n0, s * 64, 2);
    }
    gridbar(gen);
    // ---------- MLP L2: [B,256], K=512 (8 slices of 64); A = leaky(sum16) --
#pragma unroll 1
    for (int tl = bid; tl < 2 * 2 * 4 * 8; tl += nblk) {
        int br = tl / 64, r = tl % 64;
        int s = r & 7; r >>= 3;
        int n0 = (r % 4) * 64, m0 = (r / 4) * 64;
        const float* W = br ? lv_W2 : mu_W2;
        const float* bb = br ? lv_b2 : mu_b2;
        const float* A = g_m1p + (size_t)br * 16 * (B_ * 512);
        float* C = g_m2p + ((size_t)br * 8 + s) * (B_ * 256);
        tile64(&sm, A, 512, (size_t)B_ * 512, 16, 1, W, 512, bb, s == 0, C, 256, 0, 0, m0, n0, s * 64, 2);
    }
    gridbar(gen);
    // ---------- MLP L3: [B,128], K=256 (4 slices of 64); A = leaky(sum8) ---
#pragma unroll 1
    for (int tl = bid; tl < 2 * 2 * 2 * 4; tl += nblk) {
        int br = tl / 16, r = tl % 16;
        int s = r & 3; r >>= 2;
        int n0 = (r % 2) * 64, m0 = (r / 2) * 64;
        const float* W = br ? lv_W3 : mu_W3;
        const float* bb = br ? lv_b3 : mu_b3;
        const float* A = g_m2p + (size_t)br * 8 * (B_ * 256);
        float* C = g_m3p + ((size_t)br * 4 + s) * (B_ * 128);
        tile64(&sm, A, 256, (size_t)B_ * 256, 8, 1, W, 256, bb, s == 0, C, 128, 0, 0, m0, n0, s * 64, 2);
    }
    gridbar(gen);

    // ---------- prep decoder ----------
    for (int i = gtid; i < B_ * (HDEC_ + D_); i += nthr) {
        int m = i / (HDEC_ + D_), c = i % (HDEC_ + D_);
        if (c < RU_) {
            __stcg(&g_hdec[m * HDEC_ + c], __ldcg(&g_h_phi[m * RU_ + c]));
        } else if (c < HDEC_) {
            int l = c - RU_;
            float zm = 0.f, zl = 0.f;
#pragma unroll
            for (int s = 0; s < 4; s++) {
                zm += __ldcg(&g_m3p[(size_t)(0 * 4 + s) * (B_ * 128) + m * 128 + l]);
                zl += __ldcg(&g_m3p[(size_t)(1 * 4 + s) * (B_ * 128) + m * 128 + l]);
            }
            z_mu_o[m * LD_ + l] = zm;
            z_lv_o[m * LD_ + l] = zl;
            float z = zm + __ldg(&eps[m * LD_ + l]) * expf(0.5f * zl);
            __stcg(&g_hdec[m * HDEC_ + c], z);
        } else {
            int d = c - HDEC_;
            __stcg(&g_xdec[m * D_ + d], __ldg(&past[((size_t)m * PAST_ + PAST_ - 1) * D_ + d]));
        }
    }
    gridbar(gen);

    // ---------- decoder recurrence (4 barriers / step) ----------
#pragma unroll 1
    for (int t = 0; t < TL_; t++) {
        // D1: s=0..1 Gi (K=128, 2 slices of 64; A reduces 16 out partials,
        // emits x_mu[:,t-1,:] on n0==0 tiles); s=2..11 Gh (10 slices of 64).
#pragma unroll 1
        for (int tl = bid; tl < 60 * 12; tl += nblk) {
            int s = tl % 12, r = tl / 12;
            int n0 = (r % 30) * 64, m0 = (r / 30) * 64;
            float* C = g_dghp + (size_t)s * ((size_t)B_ * G3HD);
            if (s < 2) {
                if (t == 0) {
                    tile64(&sm, g_xdec, D_, 0, 1, 0, dec_Wih, D_, dec_bih, s == 0,
                           C, G3HD, 0, 0, m0, n0, s * 64, 2);
                } else {
                    float* aux = (n0 == 0) ? (x_mu + (size_t)(t - 1) * D_) : 0;
                    tile64(&sm, g_outp, D_, (size_t)B_ * D_, 16, 0, dec_Wih, D_, dec_bih, s == 0,
                           C, G3HD, aux, TL_ * D_, m0, n0, s * 64, 2);
                }
            } else {
                int sh = s - 2;
                tile64(&sm, g_hdec, HDEC_, 0, 1, 0, dec_Whh, HDEC_, dec_bhh, sh == 0,
                       C, G3HD, 0, 0, m0, n0, sh * 64, 2);
            }
        }
        gridbar(gen);
        // D2: GRU pointwise, float4 (Gi = slices 0..1, Gh = slices 2..11)
        const int Q = HDEC_ / 4;   // 160
        for (int i = gtid; i < B_ * Q; i += nthr) {
            int m = i / Q, j = (i % Q) * 4;
            float4 ir = make_float4(0.f,0.f,0.f,0.f), iz = ir, in = ir;
            float4 hr = ir, hz = ir, hn = ir;
#pragma unroll
            for (int s = 0; s < 12; s++) {
                const float* gp = g_dghp + (size_t)s * ((size_t)B_ * G3HD) + (size_t)m * G3HD;
                float4 a = ld4cg(gp + j);
                float4 b = ld4cg(gp + HDEC_ + j);
                float4 c = ld4cg(gp + 2 * HDEC_ + j);
                if (s < 2) {
                    ir.x+=a.x; ir.y+=a.y; ir.z+=a.z; ir.w+=a.w;
                    iz.x+=b.x; iz.y+=b.y; iz.z+=b.z; iz.w+=b.w;
                    in.x+=c.x; in.y+=c.y; in.z+=c.z; in.w+=c.w;
                } else {
                    hr.x+=a.x; hr.y+=a.y; hr.z+=a.z; hr.w+=a.w;
                    hz.x+=b.x; hz.y+=b.y; hz.z+=b.z; hz.w+=b.w;
                    hn.x+=c.x; hn.y+=c.y; hn.z+=c.z; hn.w+=c.w;
                }
            }
            float* hp = &g_hdec[(size_t)m * HDEC_ + j];
            float4 hv = ld4cg(hp);
            float4 o;
            { float rr = sigm(ir.x + hr.x), zz = sigm(iz.x + hz.x);
              float nn = tanhf(in.x + rr * hn.x); o.x = (1.f - zz) * nn + zz * hv.x; }
            { float rr = sigm(ir.y + hr.y), zz = sigm(iz.y + hz.y);
              float nn = tanhf(in.y + rr * hn.y); o.y = (1.f - zz) * nn + zz * hv.y; }
            { float rr = sigm(ir.z + hr.z), zz = sigm(iz.z + hz.z);
              float nn = tanhf(in.z + rr * hn.z); o.z = (1.f - zz) * nn + zz * hv.z; }
            { float rr = sigm(ir.w + hr.w), zz = sigm(iz.w + hz.w);
              float nn = tanhf(in.w + rr * hn.w); o.w = (1.f - zz) * nn + zz * hv.w; }
            st4cg(hp, o);
        }
        gridbar(gen);
        // D3: fc partials [B,512], K=640 (20 slices of 32, nchunk=1)
#pragma unroll 1
        for (int tl = bid; tl < 2 * 8 * 20; tl += nblk) {
            int s = tl % 20, r = tl / 20;
            int n0 = (r % 8) * 64, m0 = (r / 8) * 64;
            float* C = g_fcp + (size_t)s * ((size_t)B_ * FCN_);
            tile64(&sm, g_hdec, HDEC_, 0, 1, 0, fc_W, HDEC_, fc_b, s == 0, C, FCN_, 0, 0,
                   m0, n0, s * 32, 1);
        }
        gridbar(gen);
        // D4: out partials [B,128], K=512 (16 slices of 32); A = relu(sum20)
#pragma unroll 1
        for (int tl = bid; tl < 2 * 2 * 16; tl += nblk) {
            int s = tl % 16, r = tl / 16;
            int n0 = (r % 2) * 64, m0 = (r / 2) * 64;
            float* C = g_outp + (size_t)s * (B_ * D_);
            tile64(&sm, g_fcp, FCN_, (size_t)B_ * FCN_, 20, 2, out_W, FCN_, out_b, s == 0,
                   C, D_, 0, 0, m0, n0, s * 32, 1);
        }
        gridbar(gen);
    }

    // ---------- final x_mu[:, TL-1, :] ----------
    for (int i = gtid; i < B_ * D_ / 4; i += nthr) {
        int m = i / 32, d = (i % 32) * 4;
        float4 v = make_float4(0.f,0.f,0.f,0.f);
#pragma unroll
        for (int s = 0; s < 16; s++) {
            float4 u = ld4cg(&g_outp[(size_t)s * B_ * D_ + m * D_ + d]);
            v.x+=u.x; v.y+=u.y; v.z+=u.z; v.w+=u.w;
        }
        *(float4*)&x_mu[((size_t)m * TL_ + TL_ - 1) * D_ + d] = v;
    }
}

// ---------------- host launch: single graph node ---------------------------
extern "C" void kernel_launch(void* const* d_in, const int* in_sizes, int n_in,
                              void* d_out, int out_size)
{
    (void)in_sizes; (void)n_in; (void)out_size;
    const float* past    = (const float*)d_in[0];
    const float* future  = (const float*)d_in[1];
    const float* eps     = (const float*)d_in[2];
    const float* phi_Wih = (const float*)d_in[3];
    const float* phi_Whh = (const float*)d_in[4];
    const float* phi_bih = (const float*)d_in[5];
    const float* phi_bhh = (const float*)d_in[6];
    const float* xr_Wih  = (const float*)d_in[7];
    const float* xr_Whh  = (const float*)d_in[8];
    const float* xr_bih  = (const float*)d_in[9];
    const float* xr_bhh  = (const float*)d_in[10];
    const float* mu_W1   = (const float*)d_in[11];
    const float* mu_b1   = (const float*)d_in[12];
    const float* mu_W2   = (const float*)d_in[13];
    const float* mu_b2   = (const float*)d_in[14];
    const float* mu_W3   = (const float*)d_in[15];
    const float* mu_b3   = (const float*)d_in[16];
    const float* lv_W1   = (const float*)d_in[17];
    const float* lv_b1   = (const float*)d_in[18];
    const float* lv_W2   = (const float*)d_in[19];
    const float* lv_b2   = (const float*)d_in[20];
    const float* lv_W3   = (const float*)d_in[21];
    const float* lv_b3   = (const float*)d_in[22];
    const float* dec_Wih = (const float*)d_in[23];
    const float* dec_Whh = (const float*)d_in[24];
    const float* dec_bih = (const float*)d_in[25];
    const float* dec_bhh = (const float*)d_in[26];
    const float* fc_W    = (const float*)d_in[27];
    const float* fc_b    = (const float*)d_in[28];
    const float* out_W   = (const float*)d_in[29];
    const float* out_b   = (const float*)d_in[30];

    float* outp = (float*)d_out;
    float* x_mu = outp;
    float* z_mu = outp + (size_t)B_ * TL_ * D_;
    float* z_lv = z_mu + (size_t)B_ * LD_;

    int dev = 0, sms = 148;
    cudaGetDevice(&dev);
    cudaDeviceGetAttribute(&sms, cudaDevAttrMultiProcessorCount, dev);
    int nblk = sms * 8;
    if (nblk > MAXBLK) nblk = MAXBLK;

    vae_persistent<<<nblk, 64>>>(
        past, future, eps,
        phi_Wih, phi_Whh, phi_bih, phi_bhh,
        xr_Wih, xr_Whh, xr_bih, xr_bhh,
        mu_W1, mu_b1, mu_W2, mu_b2, mu_W3, mu_b3,
        lv_W1, lv_b1, lv_W2, lv_b2, lv_W3, lv_b3,
        dec_Wih, dec_Whh, dec_bih, dec_bhh,
        fc_W, fc_b, out_W, out_b,
        x_mu, z_mu, z_lv);
}

// round 12
// speedup vs baseline: 1.2711x; 1.2711x over previous
#include <cuda_runtime.h>
#include <math.h>

#define B_    128
#define PAST_ 256
#define FUT_  128
#define D_    128
#define RU_   512
#define LD_   128
#define FCN_  512
#define TL_   128
#define HDEC_ 640
#define G3RU  1536
#define G3HD  1920
#define MAXBLK 2048

// ---------------- static device scratch (no allocations anywhere) ----------
__device__ float g_gi_phi[(size_t)B_ * PAST_ * G3RU];      // 201 MB
__device__ float g_gi_xr [(size_t)B_ * FUT_  * G3RU];      // 100 MB
__device__ float g_h_phi [B_ * RU_];
__device__ float g_h_xr  [B_ * RU_];
__device__ float g_feat  [B_ * 2 * RU_];
__device__ float g_ghp   [(size_t)2 * 8 * B_ * G3RU];      // enc gh partials [g][s<8]
__device__ float g_m1p   [(size_t)2 * 16 * B_ * 512];
__device__ float g_m2p   [2 * 8 * B_ * 256];
__device__ float g_m3p   [2 * 4 * B_ * 128];
__device__ float g_hdec  [B_ * HDEC_];
__device__ float g_xdec  [B_ * D_];
__device__ float g_dghp  [(size_t)12 * B_ * G3HD];         // dec: s=0..1 Gi, s=2..11 Gh
__device__ float g_fcp   [(size_t)20 * B_ * FCN_];
__device__ float g_outp  [16 * B_ * D_];
__device__ unsigned g_slots[MAXBLK];

// ---------------- polite lock-free grid barrier ----------------------------
__device__ __forceinline__ void gridbar(unsigned &gen) {
    gen++;
    __syncthreads();
    __threadfence();
    if (threadIdx.x == 0) *(volatile unsigned*)&g_slots[blockIdx.x] = gen;
    if (threadIdx.x < 32) {
        const int nb = gridDim.x;
        unsigned delay = 32;
        for (;;) {
            bool done = true;
            for (int s = threadIdx.x; s < nb; s += 32)
                if (*(volatile unsigned*)&g_slots[s] < gen) done = false;
            if (__all_sync(0xffffffffu, done)) break;
            __nanosleep(delay);
            if (delay < 1024) delay <<= 1;
        }
        __threadfence();
    }
    __syncthreads();
}

__device__ __forceinline__ float actf(float v, int act) {
    if (act == 1) return v > 0.f ? v : 0.01f * v;   // leaky_relu
    if (act == 2) return fmaxf(v, 0.f);             // relu
    return v;
}
__device__ __forceinline__ float sigm(float x) { return 1.f / (1.f + expf(-x)); }

__device__ __forceinline__ float4 ld4cg(const float* p) { return __ldcg((const float4*)p); }
__device__ __forceinline__ float4 ld4g (const float* p) { return __ldg ((const float4*)p); }
__device__ __forceinline__ void st4cg(float* p, float4 v) { __stcg((float4*)p, v); }

// packed f32x2 FMA: two fp32 fmaf per instruction, RN rounding each half
__device__ __forceinline__ unsigned long long ffma2(
    unsigned long long a, unsigned long long b, unsigned long long c)
{
    unsigned long long d;
    asm("fma.rn.f32x2 %0, %1, %2, %3;" : "=l"(d) : "l"(a), "l"(b), "l"(c));
    return d;
}
__device__ __forceinline__ unsigned long long dup32(float x) {
    unsigned long long r;
    asm("mov.b64 %0, {%1, %1};" : "=l"(r) : "f"(x));
    return r;
}
__device__ __forceinline__ float2 unpk(unsigned long long u) {
    float2 f;
    asm("mov.b64 {%0, %1}, %2;" : "=f"(f.x), "=f"(f.y) : "l"(u));
    return f;
}

// ---------------- 64x64 tile GEMM, 128 threads, 4x8/thread, f32x2 ----------
// C[m0..+64, n0..+64] = A[:, k0..+32*nchunk] @ W[:, ...]^T (+bias if addBias)
// A-loader optionally reduces nred partials (stride pstride, activation actIn)
// and, if aux != null, writes the reduced (pre-activation) A values to aux.
// A stored plain in smem; FFMA2 (a,a) operand built via mov.b64 (ALU pipe).
struct Smem2 {
    float As[32][68];   // [k][row], padded: 8.7 KB
    float Ws[32][68];   // [k][col]: 8.7 KB
};

__device__ __noinline__ void tile64(
    Smem2* sm,
    const float* __restrict__ A, int ldA, size_t pstride, int nred, int actIn,
    const float* __restrict__ W, int ldW,
    const float* __restrict__ bias, int addBias,
    float* __restrict__ C, int ldC,
    float* __restrict__ aux, int auxLd,
    int m0, int n0, int k0, int nchunk)
{
    const int tid = threadIdx.x;          // 0..127
    const int tx = tid & 7;               // col group (8 cols each)
    const int ty = tid >> 3;              // row group (4 rows each), 0..15

    unsigned long long acc[4][4];
#pragma unroll
    for (int i = 0; i < 4; i++)
#pragma unroll
        for (int j = 0; j < 4; j++) acc[i][j] = 0ull;

#pragma unroll 1
    for (int ch = 0; ch < nchunk; ch++) {
        const int kb = k0 + ch * 32;
        // ---- stage chunk: 64 rows x 32 k for A and W, transposed to [k][row]
#pragma unroll
        for (int j = 0; j < 4; j++) {
            int e = tid + j * 128;
            int row = e >> 3;
            int c4 = (e & 7) * 4;
            const float* ap = A + (size_t)(m0 + row) * ldA + kb + c4;
            float4 v = ld4cg(ap);
            if (nred > 1) {
                for (int q = 1; q < nred; q++) {
                    float4 u = ld4cg(ap + (size_t)q * pstride + c4 - c4);
                    u = ld4cg(ap + (size_t)q * pstride);
                    v.x += u.x; v.y += u.y; v.z += u.z; v.w += u.w;
                }
            }
            if (aux) st4cg(aux + (size_t)(m0 + row) * auxLd + kb + c4, v);
            sm->As[c4 + 0][row] = actf(v.x, actIn);
            sm->As[c4 + 1][row] = actf(v.y, actIn);
            sm->As[c4 + 2][row] = actf(v.z, actIn);
            sm->As[c4 + 3][row] = actf(v.w, actIn);
            float4 w = ld4g(W + (size_t)(n0 + row) * ldW + kb + c4);
            sm->Ws[c4 + 0][row] = w.x;
            sm->Ws[c4 + 1][row] = w.y;
            sm->Ws[c4 + 2][row] = w.z;
            sm->Ws[c4 + 3][row] = w.w;
        }
        __syncthreads();
#pragma unroll 8
        for (int kk = 0; kk < 32; kk++) {
            float4 av = *(const float4*)&sm->As[kk][ty * 4];
            longlong2 wA = *(const longlong2*)&sm->Ws[kk][tx * 8];
            longlong2 wB = *(const longlong2*)&sm->Ws[kk][tx * 8 + 4];
            const unsigned long long w0 = (unsigned long long)wA.x;
            const unsigned long long w1 = (unsigned long long)wA.y;
            const unsigned long long w2 = (unsigned long long)wB.x;
            const unsigned long long w3 = (unsigned long long)wB.y;
            unsigned long long a0 = dup32(av.x);
            unsigned long long a1 = dup32(av.y);
            unsigned long long a2 = dup32(av.z);
            unsigned long long a3 = dup32(av.w);
            acc[0][0] = ffma2(a0, w0, acc[0][0]);
            acc[0][1] = ffma2(a0, w1, acc[0][1]);
            acc[0][2] = ffma2(a0, w2, acc[0][2]);
            acc[0][3] = ffma2(a0, w3, acc[0][3]);
            acc[1][0] = ffma2(a1, w0, acc[1][0]);
            acc[1][1] = ffma2(a1, w1, acc[1][1]);
            acc[1][2] = ffma2(a1, w2, acc[1][2]);
            acc[1][3] = ffma2(a1, w3, acc[1][3]);
            acc[2][0] = ffma2(a2, w0, acc[2][0]);
            acc[2][1] = ffma2(a2, w1, acc[2][1]);
            acc[2][2] = ffma2(a2, w2, acc[2][2]);
            acc[2][3] = ffma2(a2, w3, acc[2][3]);
            acc[3][0] = ffma2(a3, w0, acc[3][0]);
            acc[3][1] = ffma2(a3, w1, acc[3][1]);
            acc[3][2] = ffma2(a3, w2, acc[3][2]);
            acc[3][3] = ffma2(a3, w3, acc[3][3]);
        }
        __syncthreads();
    }

    const int n = n0 + tx * 8;
    float4 b0 = make_float4(0.f, 0.f, 0.f, 0.f), b1 = b0;
    if (addBias) { b0 = ld4g(bias + n); b1 = ld4g(bias + n + 4); }
#pragma unroll
    for (int i = 0; i < 4; i++) {
        const int m = m0 + ty * 4 + i;
        float2 p0 = unpk(acc[i][0]), p1 = unpk(acc[i][1]);
        float2 p2 = unpk(acc[i][2]), p3 = unpk(acc[i][3]);
        float4 v0 = make_float4(p0.x + b0.x, p0.y + b0.y, p1.x + b0.z, p1.y + b0.w);
        float4 v1 = make_float4(p2.x + b1.x, p2.y + b1.y, p3.x + b1.z, p3.y + b1.w);
        st4cg(C + (size_t)m * ldC + n, v0);
        st4cg(C + (size_t)m * ldC + n + 4, v1);
    }
}

// ---------------- persistent kernel ---------------------------------------
__global__ void __launch_bounds__(128, 4) vae_persistent(
    const float* __restrict__ past, const float* __restrict__ future,
    const float* __restrict__ eps,
    const float* __restrict__ phi_Wih, const float* __restrict__ phi_Whh,
    const float* __restrict__ phi_bih, const float* __restrict__ phi_bhh,
    const float* __restrict__ xr_Wih,  const float* __restrict__ xr_Whh,
    const float* __restrict__ xr_bih,  const float* __restrict__ xr_bhh,
    const float* __restrict__ mu_W1, const float* __restrict__ mu_b1,
    const float* __restrict__ mu_W2, const float* __restrict__ mu_b2,
    const float* __restrict__ mu_W3, const float* __restrict__ mu_b3,
    const float* __restrict__ lv_W1, const float* __restrict__ lv_b1,
    const float* __restrict__ lv_W2, const float* __restrict__ lv_b2,
    const float* __restrict__ lv_W3, const float* __restrict__ lv_b3,
    const float* __restrict__ dec_Wih, const float* __restrict__ dec_Whh,
    const float* __restrict__ dec_bih, const float* __restrict__ dec_bhh,
    const float* __restrict__ fc_W, const float* __restrict__ fc_b,
    const float* __restrict__ out_W, const float* __restrict__ out_b,
    float* __restrict__ x_mu, float* __restrict__ z_mu_o, float* __restrict__ z_lv_o)
{
    __shared__ Smem2 sm;
    const int nblk = gridDim.x;
    const int bid  = blockIdx.x;
    const int tid  = threadIdx.x;
    const int gtid = bid * 128 + tid;
    const int nthr = nblk * 128;

    unsigned gen = *(volatile unsigned*)&g_slots[bid];

    // ---------- P0: time-parallel input projections + zero hidden ----------
    {
        const int T1 = (B_ * PAST_ / 64) * (G3RU / 64);   // 512*24 = 12288
        const int T2 = (B_ * FUT_  / 64) * (G3RU / 64);   // 256*24 = 6144
#pragma unroll 1
        for (int tl = bid; tl < T1 + T2; tl += nblk) {
            if (tl < T1) {
                int m0 = (tl / 24) * 64, n0 = (tl % 24) * 64;
                tile64(&sm, past, D_, 0, 1, 0, phi_Wih, D_, phi_bih, 1,
                       g_gi_phi, G3RU, 0, 0, m0, n0, 0, 4);
            } else {
                int r = tl - T1;
                int m0 = (r / 24) * 64, n0 = (r % 24) * 64;
                tile64(&sm, future, D_, 0, 1, 0, xr_Wih, D_, xr_bih, 1,
                       g_gi_xr, G3RU, 0, 0, m0, n0, 0, 4);
            }
        }
        for (int i = gtid; i < 2 * B_ * RU_ / 4; i += nthr) {
            float4 z = make_float4(0.f, 0.f, 0.f, 0.f);
            if (i < B_ * RU_ / 4) st4cg(&g_h_phi[i * 4], z);
            else                  st4cg(&g_h_xr[(i - B_ * RU_ / 4) * 4], z);
        }
    }
    gridbar(gen);

    // ---------- encoder recurrences ----------
#pragma unroll 1
    for (int t = 0; t < PAST_; t++) {
        const int ngru = (t < FUT_) ? 2 : 1;
        const int TT = 2 * 24 * 8;   // m x n x ksplit = 384 per GRU
#pragma unroll 1
        for (int tl = bid; tl < ngru * TT; tl += nblk) {
            int g = tl / TT, r = tl % TT;
            int s = r & 7; r >>= 3;                    // 8 K-slices of 64 (nchunk=2)
            int n0 = (r % 24) * 64, m0 = (r / 24) * 64;
            const float* A  = g ? g_h_xr : g_h_phi;
            const float* W  = g ? xr_Whh : phi_Whh;
            const float* bb = g ? xr_bhh : phi_bhh;
            float* C = g_ghp + ((size_t)g * 8 + s) * ((size_t)B_ * G3RU);
            tile64(&sm, A, RU_, 0, 1, 0, W, RU_, bb, s == 0, C, G3RU, 0, 0, m0, n0, s * 64, 2);
        }
        gridbar(gen);
        // GRU pointwise, float4, reduce 8 slices
        const int Q = RU_ / 4;   // 128
        for (int i = gtid; i < ngru * B_ * Q; i += nthr) {
            int g = i / (B_ * Q), r = i % (B_ * Q);
            int m = r / Q, j = (r % Q) * 4;
            float4 sr = make_float4(0.f,0.f,0.f,0.f), sz = sr, sn = sr;
#pragma unroll
            for (int s = 0; s < 8; s++) {
                const float* gp = g_ghp + ((size_t)g * 8 + s) * ((size_t)B_ * G3RU) + (size_t)m * G3RU;
                float4 a = ld4cg(gp + j);
                float4 b = ld4cg(gp + RU_ + j);
                float4 c = ld4cg(gp + 2 * RU_ + j);
                sr.x+=a.x; sr.y+=a.y; sr.z+=a.z; sr.w+=a.w;
                sz.x+=b.x; sz.y+=b.y; sz.z+=b.z; sz.w+=b.w;
                sn.x+=c.x; sn.y+=c.y; sn.z+=c.z; sn.w+=c.w;
            }
            const float* gim = g ? (g_gi_xr  + ((size_t)m * FUT_  + t) * G3RU)
                                 : (g_gi_phi + ((size_t)m * PAST_ + t) * G3RU);
            float4 ir = ld4cg(gim + j), iz = ld4cg(gim + RU_ + j), in = ld4cg(gim + 2 * RU_ + j);
            float* hp = (g ? g_h_xr : g_h_phi) + (size_t)m * RU_ + j;
            float4 hv = ld4cg(hp);
            float4 o;
            { float rr = sigm(ir.x + sr.x), zz = sigm(iz.x + sz.x);
              float nn = tanhf(in.x + rr * sn.x); o.x = (1.f - zz) * nn + zz * hv.x; }
            { float rr = sigm(ir.y + sr.y), zz = sigm(iz.y + sz.y);
              float nn = tanhf(in.y + rr * sn.y); o.y = (1.f - zz) * nn + zz * hv.y; }
            { float rr = sigm(ir.z + sr.z), zz = sigm(iz.z + sz.z);
              float nn = tanhf(in.z + rr * sn.z); o.z = (1.f - zz) * nn + zz * hv.z; }
            { float rr = sigm(ir.w + sr.w), zz = sigm(iz.w + sz.w);
              float nn = tanhf(in.w + rr * sn.w); o.w = (1.f - zz) * nn + zz * hv.w; }
            st4cg(hp, o);
        }
        gridbar(gen);
    }

    // ---------- features ----------
    for (int i = gtid; i < B_ * 2 * RU_ / 4; i += nthr) {
        int m = i / (2 * RU_ / 4), c = (i % (2 * RU_ / 4)) * 4;
        float4 v = (c < RU_) ? ld4cg(&g_h_phi[m * RU_ + c]) : ld4cg(&g_h_xr[m * RU_ + c - RU_]);
        st4cg(&g_feat[m * 2 * RU_ + c], v);
    }
    gridbar(gen);

    // ---------- MLP L1: [B,512], K=1024 (16 slices of 64, nchunk=2) --------
#pragma unroll 1
    for (int tl = bid; tl < 2 * 2 * 8 * 16; tl += nblk) {
        int br = tl / 256, r = tl % 256;
        int s = r & 15; r >>= 4;
        int n0 = (r % 8) * 64, m0 = (r / 8) * 64;
        const float* W = br ? lv_W1 : mu_W1;
        const float* bb = br ? lv_b1 : mu_b1;
        float* C = g_m1p + ((size_t)br * 16 + s) * (B_ * 512);
        tile64(&sm, g_feat, 2 * RU_, 0, 1, 0, W, 2 * RU_, bb, s == 0, C, 512, 0, 0, m0, n0, s * 64, 2);
    }
    gridbar(gen);
    // ---------- MLP L2: [B,256], K=512 (8 slices of 64); A = leaky(sum16) --
#pragma unroll 1
    for (int tl = bid; tl < 2 * 2 * 4 * 8; tl += nblk) {
        int br = tl / 64, r = tl % 64;
        int s = r & 7; r >>= 3;
        int n0 = (r % 4) * 64, m0 = (r / 4) * 64;
        const float* W = br ? lv_W2 : mu_W2;
        const float* bb = br ? lv_b2 : mu_b2;
        const float* A = g_m1p + (size_t)br * 16 * (B_ * 512);
        float* C = g_m2p + ((size_t)br * 8 + s) * (B_ * 256);
        tile64(&sm, A, 512, (size_t)B_ * 512, 16, 1, W, 512, bb, s == 0, C, 256, 0, 0, m0, n0, s * 64, 2);
    }
    gridbar(gen);
    // ---------- MLP L3: [B,128], K=256 (4 slices of 64); A = leaky(sum8) ---
#pragma unroll 1
    for (int tl = bid; tl < 2 * 2 * 2 * 4; tl += nblk) {
        int br = tl / 16, r = tl % 16;
        int s = r & 3; r >>= 2;
        int n0 = (r % 2) * 64, m0 = (r / 2) * 64;
        const float* W = br ? lv_W3 : mu_W3;
        const float* bb = br ? lv_b3 : mu_b3;
        const float* A = g_m2p + (size_t)br * 8 * (B_ * 256);
        float* C = g_m3p + ((size_t)br * 4 + s) * (B_ * 128);
        tile64(&sm, A, 256, (size_t)B_ * 256, 8, 1, W, 256, bb, s == 0, C, 128, 0, 0, m0, n0, s * 64, 2);
    }
    gridbar(gen);

    // ---------- prep decoder ----------
    for (int i = gtid; i < B_ * (HDEC_ + D_); i += nthr) {
        int m = i / (HDEC_ + D_), c = i % (HDEC_ + D_);
        if (c < RU_) {
            __stcg(&g_hdec[m * HDEC_ + c], __ldcg(&g_h_phi[m * RU_ + c]));
        } else if (c < HDEC_) {
            int l = c - RU_;
            float zm = 0.f, zl = 0.f;
#pragma unroll
            for (int s = 0; s < 4; s++) {
                zm += __ldcg(&g_m3p[(size_t)(0 * 4 + s) * (B_ * 128) + m * 128 + l]);
                zl += __ldcg(&g_m3p[(size_t)(1 * 4 + s) * (B_ * 128) + m * 128 + l]);
            }
            z_mu_o[m * LD_ + l] = zm;
            z_lv_o[m * LD_ + l] = zl;
            float z = zm + __ldg(&eps[m * LD_ + l]) * expf(0.5f * zl);
            __stcg(&g_hdec[m * HDEC_ + c], z);
        } else {
            int d = c - HDEC_;
            __stcg(&g_xdec[m * D_ + d], __ldg(&past[((size_t)m * PAST_ + PAST_ - 1) * D_ + d]));
        }
    }
    gridbar(gen);

    // ---------- decoder recurrence (4 barriers / step) ----------
#pragma unroll 1
    for (int t = 0; t < TL_; t++) {
        // D1: s=0..1 Gi (K=128, 2 slices of 64; A reduces 16 out partials,
        // emits x_mu[:,t-1,:] on n0==0 tiles); s=2..11 Gh (10 slices of 64).
#pragma unroll 1
        for (int tl = bid; tl < 60 * 12; tl += nblk) {
            int s = tl % 12, r = tl / 12;
            int n0 = (r % 30) * 64, m0 = (r / 30) * 64;
            float* C = g_dghp + (size_t)s * ((size_t)B_ * G3HD);
            if (s < 2) {
                if (t == 0) {
                    tile64(&sm, g_xdec, D_, 0, 1, 0, dec_Wih, D_, dec_bih, s == 0,
                           C, G3HD, 0, 0, m0, n0, s * 64, 2);
                } else {
                    float* aux = (n0 == 0) ? (x_mu + (size_t)(t - 1) * D_) : 0;
                    tile64(&sm, g_outp, D_, (size_t)B_ * D_, 16, 0, dec_Wih, D_, dec_bih, s == 0,
                           C, G3HD, aux, TL_ * D_, m0, n0, s * 64, 2);
                }
            } else {
                int sh = s - 2;
                tile64(&sm, g_hdec, HDEC_, 0, 1, 0, dec_Whh, HDEC_, dec_bhh, sh == 0,
                       C, G3HD, 0, 0, m0, n0, sh * 64, 2);
            }
        }
        gridbar(gen);
        // D2: GRU pointwise, float4 (Gi = slices 0..1, Gh = slices 2..11)
        const int Q = HDEC_ / 4;   // 160
        for (int i = gtid; i < B_ * Q; i += nthr) {
            int m = i / Q, j = (i % Q) * 4;
            float4 ir = make_float4(0.f,0.f,0.f,0.f), iz = ir, in = ir;
            float4 hr = ir, hz = ir, hn = ir;
#pragma unroll
            for (int s = 0; s < 12; s++) {
                const float* gp = g_dghp + (size_t)s * ((size_t)B_ * G3HD) + (size_t)m * G3HD;
                float4 a = ld4cg(gp + j);
                float4 b = ld4cg(gp + HDEC_ + j);
                float4 c = ld4cg(gp + 2 * HDEC_ + j);
                if (s < 2) {
                    ir.x+=a.x; ir.y+=a.y; ir.z+=a.z; ir.w+=a.w;
                    iz.x+=b.x; iz.y+=b.y; iz.z+=b.z; iz.w+=b.w;
                    in.x+=c.x; in.y+=c.y; in.z+=c.z; in.w+=c.w;
                } else {
                    hr.x+=a.x; hr.y+=a.y; hr.z+=a.z; hr.w+=a.w;
                    hz.x+=b.x; hz.y+=b.y; hz.z+=b.z; hz.w+=b.w;
                    hn.x+=c.x; hn.y+=c.y; hn.z+=c.z; hn.w+=c.w;
                }
            }
            float* hp = &g_hdec[(size_t)m * HDEC_ + j];
            float4 hv = ld4cg(hp);
            float4 o;
            { float rr = sigm(ir.x + hr.x), zz = sigm(iz.x + hz.x);
              float nn = tanhf(in.x + rr * hn.x); o.x = (1.f - zz) * nn + zz * hv.x; }
            { float rr = sigm(ir.y + hr.y), zz = sigm(iz.y + hz.y);
              float nn = tanhf(in.y + rr * hn.y); o.y = (1.f - zz) * nn + zz * hv.y; }
            { float rr = sigm(ir.z + hr.z), zz = sigm(iz.z + hz.z);
              float nn = tanhf(in.z + rr * hn.z); o.z = (1.f - zz) * nn + zz * hv.z; }
            { float rr = sigm(ir.w + hr.w), zz = sigm(iz.w + hz.w);
              float nn = tanhf(in.w + rr * hn.w); o.w = (1.f - zz) * nn + zz * hv.w; }
            st4cg(hp, o);
        }
        gridbar(gen);
        // D3: fc partials [B,512], K=640 (20 slices of 32, nchunk=1)
#pragma unroll 1
        for (int tl = bid; tl < 2 * 8 * 20; tl += nblk) {
            int s = tl % 20, r = tl / 20;
            int n0 = (r % 8) * 64, m0 = (r / 8) * 64;
            float* C = g_fcp + (size_t)s * ((size_t)B_ * FCN_);
            tile64(&sm, g_hdec, HDEC_, 0, 1, 0, fc_W, HDEC_, fc_b, s == 0, C, FCN_, 0, 0,
                   m0, n0, s * 32, 1);
        }
        gridbar(gen);
        // D4: out partials [B,128], K=512 (16 slices of 32); A = relu(sum20)
#pragma unroll 1
        for (int tl = bid; tl < 2 * 2 * 16; tl += nblk) {
            int s = tl % 16, r = tl / 16;
            int n0 = (r % 2) * 64, m0 = (r / 2) * 64;
            float* C = g_outp + (size_t)s * (B_ * D_);
            tile64(&sm, g_fcp, FCN_, (size_t)B_ * FCN_, 20, 2, out_W, FCN_, out_b, s == 0,
                   C, D_, 0, 0, m0, n0, s * 32, 1);
        }
        gridbar(gen);
    }

    // ---------- final x_mu[:, TL-1, :] ----------
    for (int i = gtid; i < B_ * D_ / 4; i += nthr) {
        int m = i / 32, d = (i % 32) * 4;
        float4 v = make_float4(0.f,0.f,0.f,0.f);
#pragma unroll
        for (int s = 0; s < 16; s++) {
            float4 u = ld4cg(&g_outp[(size_t)s * B_ * D_ + m * D_ + d]);
            v.x+=u.x; v.y+=u.y; v.z+=u.z; v.w+=u.w;
        }
        *(float4*)&x_mu[((size_t)m * TL_ + TL_ - 1) * D_ + d] = v;
    }
}

// ---------------- host launch: single graph node ---------------------------
extern "C" void kernel_launch(void* const* d_in, const int* in_sizes, int n_in,
                              void* d_out, int out_size)
{
    (void)in_sizes; (void)n_in; (void)out_size;
    const float* past    = (const float*)d_in[0];
    const float* future  = (const float*)d_in[1];
    const float* eps     = (const float*)d_in[2];
    const float* phi_Wih = (const float*)d_in[3];
    const float* phi_Whh = (const float*)d_in[4];
    const float* phi_bih = (const float*)d_in[5];
    const float* phi_bhh = (const float*)d_in[6];
    const float* xr_Wih  = (const float*)d_in[7];
    const float* xr_Whh  = (const float*)d_in[8];
    const float* xr_bih  = (const float*)d_in[9];
    const float* xr_bhh  = (const float*)d_in[10];
    const float* mu_W1   = (const float*)d_in[11];
    const float* mu_b1   = (const float*)d_in[12];
    const float* mu_W2   = (const float*)d_in[13];
    const float* mu_b2   = (const float*)d_in[14];
    const float* mu_W3   = (const float*)d_in[15];
    const float* mu_b3   = (const float*)d_in[16];
    const float* lv_W1   = (const float*)d_in[17];
    const float* lv_b1   = (const float*)d_in[18];
    const float* lv_W2   = (const float*)d_in[19];
    const float* lv_b2   = (const float*)d_in[20];
    const float* lv_W3   = (const float*)d_in[21];
    const float* lv_b3   = (const float*)d_in[22];
    const float* dec_Wih = (const float*)d_in[23];
    const float* dec_Whh = (const float*)d_in[24];
    const float* dec_bih = (const float*)d_in[25];
    const float* dec_bhh = (const float*)d_in[26];
    const float* fc_W    = (const float*)d_in[27];
    const float* fc_b    = (const float*)d_in[28];
    const float* out_W   = (const float*)d_in[29];
    const float* out_b   = (const float*)d_in[30];

    float* outp = (float*)d_out;
    float* x_mu = outp;
    float* z_mu = outp + (size_t)B_ * TL_ * D_;
    float* z_lv = z_mu + (size_t)B_ * LD_;

    int dev = 0, sms = 148;
    cudaGetDevice(&dev);
    cudaDeviceGetAttribute(&sms, cudaDevAttrMultiProcessorCount, dev);
    int nblk = sms * 4;
    if (nblk > MAXBLK) nblk = MAXBLK;

    vae_persistent<<<nblk, 128>>>(
        past, future, eps,
        phi_Wih, phi_Whh, phi_bih, phi_bhh,
        xr_Wih, xr_Whh, xr_bih, xr_bhh,
        mu_W1, mu_b1, mu_W2, mu_b2, mu_W3, mu_b3,
        lv_W1, lv_b1, lv_W2, lv_b2, lv_W3, lv_b3,
        dec_Wih, dec_Whh, dec_bih, dec_bhh,
        fc_W, fc_b, out_W, out_b,
        x_mu, z_mu, z_lv);
}

// round 13
// speedup vs baseline: 1.5636x; 1.2301x over previous
#include <cuda_runtime.h>
#include <math.h>

#define B_    128
#define PAST_ 256
#define FUT_  128
#define D_    128
#define RU_   512
#define LD_   128
#define FCN_  512
#define TL_   128
#define HDEC_ 640
#define G3RU  1536
#define G3HD  1920
#define MAXBLK 2048

// ---------------- static device scratch (no allocations anywhere) ----------
__device__ float g_gi_phi[(size_t)B_ * PAST_ * G3RU];      // 201 MB
__device__ float g_gi_xr [(size_t)B_ * FUT_  * G3RU];      // 100 MB
__device__ float g_h_phi [B_ * RU_];
__device__ float g_h_xr  [B_ * RU_];
__device__ float g_feat  [B_ * 2 * RU_];
__device__ float g_ghp   [(size_t)2 * 8 * B_ * G3RU];      // enc gh partials [g][s<8]
__device__ float g_m1p   [(size_t)2 * 16 * B_ * 512];
__device__ float g_m2p   [2 * 8 * B_ * 256];
__device__ float g_m3p   [2 * 4 * B_ * 128];
__device__ float g_hdec  [B_ * HDEC_];
__device__ float g_xdec  [B_ * D_];
__device__ float g_dghp  [(size_t)12 * B_ * G3HD];         // dec: s=0..1 Gi, s=2..11 Gh
__device__ float g_fcp   [(size_t)20 * B_ * FCN_];
__device__ float g_outp  [16 * B_ * D_];
__device__ unsigned g_slots[MAXBLK];

// ---------------- polite lock-free grid barrier ----------------------------
__device__ __forceinline__ void gridbar(unsigned &gen) {
    gen++;
    __syncthreads();
    __threadfence();
    if (threadIdx.x == 0) *(volatile unsigned*)&g_slots[blockIdx.x] = gen;
    if (threadIdx.x < 32) {
        const int nb = gridDim.x;
        unsigned delay = 32;
        for (;;) {
            bool done = true;
            for (int s = threadIdx.x; s < nb; s += 32)
                if (*(volatile unsigned*)&g_slots[s] < gen) done = false;
            if (__all_sync(0xffffffffu, done)) break;
            __nanosleep(delay);
            if (delay < 1024) delay <<= 1;
        }
        __threadfence();
    }
    __syncthreads();
}

__device__ __forceinline__ float actf(float v, int act) {
    if (act == 1) return v > 0.f ? v : 0.01f * v;   // leaky_relu
    if (act == 2) return fmaxf(v, 0.f);             // relu
    return v;
}
__device__ __forceinline__ float sigm(float x) { return 1.f / (1.f + expf(-x)); }

__device__ __forceinline__ float4 ld4cg(const float* p) { return __ldcg((const float4*)p); }
__device__ __forceinline__ float4 ld4g (const float* p) { return __ldg ((const float4*)p); }
__device__ __forceinline__ void st4cg(float* p, float4 v) { __stcg((float4*)p, v); }

// ---------------- 64x64 tile GEMM, 128 threads, 4x8/thread, scalar ---------
// C[m0..+64, n0..+64] = A[:, k0..+32*nchunk] @ W[:, ...]^T (+bias if addBias)
// A-loader optionally reduces nred partials (stride pstride, activation actIn)
// and, if aux != null, writes the reduced (pre-activation) A values to aux.
struct Smem2 {
    float As[32][68];   // [k][row], padded: 8.7 KB
    float Ws[32][68];   // [k][col]: 8.7 KB
};

__device__ __noinline__ void tile64(
    Smem2* sm,
    const float* __restrict__ A, int ldA, size_t pstride, int nred, int actIn,
    const float* __restrict__ W, int ldW,
    const float* __restrict__ bias, int addBias,
    float* __restrict__ C, int ldC,
    float* __restrict__ aux, int auxLd,
    int m0, int n0, int k0, int nchunk)
{
    const int tid = threadIdx.x;          // 0..127
    const int tx = tid & 7;               // col group (8 cols each)
    const int ty = tid >> 3;              // row group (4 rows each), 0..15

    float acc[4][8];
#pragma unroll
    for (int i = 0; i < 4; i++)
#pragma unroll
        for (int j = 0; j < 8; j++) acc[i][j] = 0.f;

#pragma unroll 1
    for (int ch = 0; ch < nchunk; ch++) {
        const int kb = k0 + ch * 32;
        // ---- stage chunk: 64 rows x 32 k for A and W, transposed to [k][row]
#pragma unroll
        for (int j = 0; j < 4; j++) {
            int e = tid + j * 128;
            int row = e >> 3;
            int c4 = (e & 7) * 4;
            const float* ap = A + (size_t)(m0 + row) * ldA + kb + c4;
            float4 v = ld4cg(ap);
            if (nred > 1) {
                for (int q = 1; q < nred; q++) {
                    float4 u = ld4cg(ap + (size_t)q * pstride);
                    v.x += u.x; v.y += u.y; v.z += u.z; v.w += u.w;
                }
            }
            if (aux) st4cg(aux + (size_t)(m0 + row) * auxLd + kb + c4, v);
            sm->As[c4 + 0][row] = actf(v.x, actIn);
            sm->As[c4 + 1][row] = actf(v.y, actIn);
            sm->As[c4 + 2][row] = actf(v.z, actIn);
            sm->As[c4 + 3][row] = actf(v.w, actIn);
            float4 w = ld4g(W + (size_t)(n0 + row) * ldW + kb + c4);
            sm->Ws[c4 + 0][row] = w.x;
            sm->Ws[c4 + 1][row] = w.y;
            sm->Ws[c4 + 2][row] = w.z;
            sm->Ws[c4 + 3][row] = w.w;
        }
        __syncthreads();
#pragma unroll 4
        for (int kk = 0; kk < 32; kk++) {
            float4 av = *(const float4*)&sm->As[kk][ty * 4];
            float4 w0 = *(const float4*)&sm->Ws[kk][tx * 8];
            float4 w1 = *(const float4*)&sm->Ws[kk][tx * 8 + 4];
            const float a[4] = {av.x, av.y, av.z, av.w};
            const float w[8] = {w0.x, w0.y, w0.z, w0.w, w1.x, w1.y, w1.z, w1.w};
#pragma unroll
            for (int i = 0; i < 4; i++)
#pragma unroll
                for (int j = 0; j < 8; j++)
                    acc[i][j] = fmaf(a[i], w[j], acc[i][j]);
        }
        __syncthreads();
    }

    const int n = n0 + tx * 8;
    float4 b0 = make_float4(0.f, 0.f, 0.f, 0.f), b1 = b0;
    if (addBias) { b0 = ld4g(bias + n); b1 = ld4g(bias + n + 4); }
#pragma unroll
    for (int i = 0; i < 4; i++) {
        const int m = m0 + ty * 4 + i;
        float4 v0 = make_float4(acc[i][0] + b0.x, acc[i][1] + b0.y,
                                acc[i][2] + b0.z, acc[i][3] + b0.w);
        float4 v1 = make_float4(acc[i][4] + b1.x, acc[i][5] + b1.y,
                                acc[i][6] + b1.z, acc[i][7] + b1.w);
        st4cg(C + (size_t)m * ldC + n, v0);
        st4cg(C + (size_t)m * ldC + n + 4, v1);
    }
}

// ---------------- persistent kernel ---------------------------------------
__global__ void __launch_bounds__(128, 4) vae_persistent(
    const float* __restrict__ past, const float* __restrict__ future,
    const float* __restrict__ eps,
    const float* __restrict__ phi_Wih, const float* __restrict__ phi_Whh,
    const float* __restrict__ phi_bih, const float* __restrict__ phi_bhh,
    const float* __restrict__ xr_Wih,  const float* __restrict__ xr_Whh,
    const float* __restrict__ xr_bih,  const float* __restrict__ xr_bhh,
    const float* __restrict__ mu_W1, const float* __restrict__ mu_b1,
    const float* __restrict__ mu_W2, const float* __restrict__ mu_b2,
    const float* __restrict__ mu_W3, const float* __restrict__ mu_b3,
    const float* __restrict__ lv_W1, const float* __restrict__ lv_b1,
    const float* __restrict__ lv_W2, const float* __restrict__ lv_b2,
    const float* __restrict__ lv_W3, const float* __restrict__ lv_b3,
    const float* __restrict__ dec_Wih, const float* __restrict__ dec_Whh,
    const float* __restrict__ dec_bih, const float* __restrict__ dec_bhh,
    const float* __restrict__ fc_W, const float* __restrict__ fc_b,
    const float* __restrict__ out_W, const float* __restrict__ out_b,
    float* __restrict__ x_mu, float* __restrict__ z_mu_o, float* __restrict__ z_lv_o)
{
    __shared__ Smem2 sm;
    const int nblk = gridDim.x;
    const int bid  = blockIdx.x;
    const int tid  = threadIdx.x;
    const int gtid = bid * 128 + tid;
    const int nthr = nblk * 128;

    unsigned gen = *(volatile unsigned*)&g_slots[bid];

    // ---------- P0: time-parallel input projections + zero hidden ----------
    {
        const int T1 = (B_ * PAST_ / 64) * (G3RU / 64);   // 512*24 = 12288
        const int T2 = (B_ * FUT_  / 64) * (G3RU / 64);   // 256*24 = 6144
#pragma unroll 1
        for (int tl = bid; tl < T1 + T2; tl += nblk) {
            if (tl < T1) {
                int m0 = (tl / 24) * 64, n0 = (tl % 24) * 64;
                tile64(&sm, past, D_, 0, 1, 0, phi_Wih, D_, phi_bih, 1,
                       g_gi_phi, G3RU, 0, 0, m0, n0, 0, 4);
            } else {
                int r = tl - T1;
                int m0 = (r / 24) * 64, n0 = (r % 24) * 64;
                tile64(&sm, future, D_, 0, 1, 0, xr_Wih, D_, xr_bih, 1,
                       g_gi_xr, G3RU, 0, 0, m0, n0, 0, 4);
            }
        }
        for (int i = gtid; i < 2 * B_ * RU_ / 4; i += nthr) {
            float4 z = make_float4(0.f, 0.f, 0.f, 0.f);
            if (i < B_ * RU_ / 4) st4cg(&g_h_phi[i * 4], z);
            else                  st4cg(&g_h_xr[(i - B_ * RU_ / 4) * 4], z);
        }
    }
    gridbar(gen);

    // ---------- encoder recurrences ----------
#pragma unroll 1
    for (int t = 0; t < PAST_; t++) {
        const int ngru = (t < FUT_) ? 2 : 1;
        const int TT = 2 * 24 * 8;   // m x n x ksplit = 384 per GRU
#pragma unroll 1
        for (int tl = bid; tl < ngru * TT; tl += nblk) {
            int g = tl / TT, r = tl % TT;
            int s = r & 7; r >>= 3;                    // 8 K-slices of 64 (nchunk=2)
            int n0 = (r % 24) * 64, m0 = (r / 24) * 64;
            const float* A  = g ? g_h_xr : g_h_phi;
            const float* W  = g ? xr_Whh : phi_Whh;
            const float* bb = g ? xr_bhh : phi_bhh;
            float* C = g_ghp + ((size_t)g * 8 + s) * ((size_t)B_ * G3RU);
            tile64(&sm, A, RU_, 0, 1, 0, W, RU_, bb, s == 0, C, G3RU, 0, 0, m0, n0, s * 64, 2);
        }
        gridbar(gen);
        // GRU pointwise, float4, reduce 8 slices
        const int Q = RU_ / 4;   // 128
        for (int i = gtid; i < ngru * B_ * Q; i += nthr) {
            int g = i / (B_ * Q), r = i % (B_ * Q);
            int m = r / Q, j = (r % Q) * 4;
            float4 sr = make_float4(0.f,0.f,0.f,0.f), sz = sr, sn = sr;
#pragma unroll
            for (int s = 0; s < 8; s++) {
                const float* gp = g_ghp + ((size_t)g * 8 + s) * ((size_t)B_ * G3RU) + (size_t)m * G3RU;
                float4 a = ld4cg(gp + j);
                float4 b = ld4cg(gp + RU_ + j);
                float4 c = ld4cg(gp + 2 * RU_ + j);
                sr.x+=a.x; sr.y+=a.y; sr.z+=a.z; sr.w+=a.w;
                sz.x+=b.x; sz.y+=b.y; sz.z+=b.z; sz.w+=b.w;
                sn.x+=c.x; sn.y+=c.y; sn.z+=c.z; sn.w+=c.w;
            }
            const float* gim = g ? (g_gi_xr  + ((size_t)m * FUT_  + t) * G3RU)
                                 : (g_gi_phi + ((size_t)m * PAST_ + t) * G3RU);
            float4 ir = ld4cg(gim + j), iz = ld4cg(gim + RU_ + j), in = ld4cg(gim + 2 * RU_ + j);
            float* hp = (g ? g_h_xr : g_h_phi) + (size_t)m * RU_ + j;
            float4 hv = ld4cg(hp);
            float4 o;
            { float rr = sigm(ir.x + sr.x), zz = sigm(iz.x + sz.x);
              float nn = tanhf(in.x + rr * sn.x); o.x = (1.f - zz) * nn + zz * hv.x; }
            { float rr = sigm(ir.y + sr.y), zz = sigm(iz.y + sz.y);
              float nn = tanhf(in.y + rr * sn.y); o.y = (1.f - zz) * nn + zz * hv.y; }
            { float rr = sigm(ir.z + sr.z), zz = sigm(iz.z + sz.z);
              float nn = tanhf(in.z + rr * sn.z); o.z = (1.f - zz) * nn + zz * hv.z; }
            { float rr = sigm(ir.w + sr.w), zz = sigm(iz.w + sz.w);
              float nn = tanhf(in.w + rr * sn.w); o.w = (1.f - zz) * nn + zz * hv.w; }
            st4cg(hp, o);
        }
        gridbar(gen);
    }

    // ---------- features ----------
    for (int i = gtid; i < B_ * 2 * RU_ / 4; i += nthr) {
        int m = i / (2 * RU_ / 4), c = (i % (2 * RU_ / 4)) * 4;
        float4 v = (c < RU_) ? ld4cg(&g_h_phi[m * RU_ + c]) : ld4cg(&g_h_xr[m * RU_ + c - RU_]);
        st4cg(&g_feat[m * 2 * RU_ + c], v);
    }
    gridbar(gen);

    // ---------- MLP L1: [B,512], K=1024 (16 slices of 64, nchunk=2) --------
#pragma unroll 1
    for (int tl = bid; tl < 2 * 2 * 8 * 16; tl += nblk) {
        int br = tl / 256, r = tl % 256;
        int s = r & 15; r >>= 4;
        int n0 = (r % 8) * 64, m0 = (r / 8) * 64;
        const float* W = br ? lv_W1 : mu_W1;
        const float* bb = br ? lv_b1 : mu_b1;
        float* C = g_m1p + ((size_t)br * 16 + s) * (B_ * 512);
        tile64(&sm, g_feat, 2 * RU_, 0, 1, 0, W, 2 * RU_, bb, s == 0, C, 512, 0, 0, m0, n0, s * 64, 2);
    }
    gridbar(gen);
    // ---------- MLP L2: [B,256], K=512 (8 slices of 64); A = leaky(sum16) --
#pragma unroll 1
    for (int tl = bid; tl < 2 * 2 * 4 * 8; tl += nblk) {
        int br = tl / 64, r = tl % 64;
        int s = r & 7; r >>= 3;
        int n0 = (r % 4) * 64, m0 = (r / 4) * 64;
        const float* W = br ? lv_W2 : mu_W2;
        const float* bb = br ? lv_b2 : mu_b2;
        const float* A = g_m1p + (size_t)br * 16 * (B_ * 512);
        float* C = g_m2p + ((size_t)br * 8 + s) * (B_ * 256);
        tile64(&sm, A, 512, (size_t)B_ * 512, 16, 1, W, 512, bb, s == 0, C, 256, 0, 0, m0, n0, s * 64, 2);
    }
    gridbar(gen);
    // ---------- MLP L3: [B,128], K=256 (4 slices of 64); A = leaky(sum8) ---
#pragma unroll 1
    for (int tl = bid; tl < 2 * 2 * 2 * 4; tl += nblk) {
        int br = tl / 16, r = tl % 16;
        int s = r & 3; r >>= 2;
        int n0 = (r % 2) * 64, m0 = (r / 2) * 64;
        const float* W = br ? lv_W3 : mu_W3;
        const float* bb = br ? lv_b3 : mu_b3;
        const float* A = g_m2p + (size_t)br * 8 * (B_ * 256);
        float* C = g_m3p + ((size_t)br * 4 + s) * (B_ * 128);
        tile64(&sm, A, 256, (size_t)B_ * 256, 8, 1, W, 256, bb, s == 0, C, 128, 0, 0, m0, n0, s * 64, 2);
    }
    gridbar(gen);

    // ---------- prep decoder ----------
    for (int i = gtid; i < B_ * (HDEC_ + D_); i += nthr) {
        int m = i / (HDEC_ + D_), c = i % (HDEC_ + D_);
        if (c < RU_) {
            __stcg(&g_hdec[m * HDEC_ + c], __ldcg(&g_h_phi[m * RU_ + c]));
        } else if (c < HDEC_) {
            int l = c - RU_;
            float zm = 0.f, zl = 0.f;
#pragma unroll
            for (int s = 0; s < 4; s++) {
                zm += __ldcg(&g_m3p[(size_t)(0 * 4 + s) * (B_ * 128) + m * 128 + l]);
                zl += __ldcg(&g_m3p[(size_t)(1 * 4 + s) * (B_ * 128) + m * 128 + l]);
            }
            z_mu_o[m * LD_ + l] = zm;
            z_lv_o[m * LD_ + l] = zl;
            float z = zm + __ldg(&eps[m * LD_ + l]) * expf(0.5f * zl);
            __stcg(&g_hdec[m * HDEC_ + c], z);
        } else {
            int d = c - HDEC_;
            __stcg(&g_xdec[m * D_ + d], __ldg(&past[((size_t)m * PAST_ + PAST_ - 1) * D_ + d]));
        }
    }
    gridbar(gen);

    // ---------- decoder recurrence (4 barriers / step) ----------
#pragma unroll 1
    for (int t = 0; t < TL_; t++) {
        // D1: s=0..1 Gi (K=128, 2 slices of 64; A reduces 16 out partials,
        // emits x_mu[:,t-1,:] on n0==0 tiles); s=2..11 Gh (10 slices of 64).
#pragma unroll 1
        for (int tl = bid; tl < 60 * 12; tl += nblk) {
            int s = tl % 12, r = tl / 12;
            int n0 = (r % 30) * 64, m0 = (r / 30) * 64;
            float* C = g_dghp + (size_t)s * ((size_t)B_ * G3HD);
            if (s < 2) {
                if (t == 0) {
                    tile64(&sm, g_xdec, D_, 0, 1, 0, dec_Wih, D_, dec_bih, s == 0,
                           C, G3HD, 0, 0, m0, n0, s * 64, 2);
                } else {
                    float* aux = (n0 == 0) ? (x_mu + (size_t)(t - 1) * D_) : 0;
                    tile64(&sm, g_outp, D_, (size_t)B_ * D_, 16, 0, dec_Wih, D_, dec_bih, s == 0,
                           C, G3HD, aux, TL_ * D_, m0, n0, s * 64, 2);
                }
            } else {
                int sh = s - 2;
                tile64(&sm, g_hdec, HDEC_, 0, 1, 0, dec_Whh, HDEC_, dec_bhh, sh == 0,
                       C, G3HD, 0, 0, m0, n0, sh * 64, 2);
            }
        }
        gridbar(gen);
        // D2: GRU pointwise, float4 (Gi = slices 0..1, Gh = slices 2..11)
        const int Q = HDEC_ / 4;   // 160
        for (int i = gtid; i < B_ * Q; i += nthr) {
            int m = i / Q, j = (i % Q) * 4;
            float4 ir = make_float4(0.f,0.f,0.f,0.f), iz = ir, in = ir;
            float4 hr = ir, hz = ir, hn = ir;
#pragma unroll
            for (int s = 0; s < 12; s++) {
                const float* gp = g_dghp + (size_t)s * ((size_t)B_ * G3HD) + (size_t)m * G3HD;
                float4 a = ld4cg(gp + j);
                float4 b = ld4cg(gp + HDEC_ + j);
                float4 c = ld4cg(gp + 2 * HDEC_ + j);
                if (s < 2) {
                    ir.x+=a.x; ir.y+=a.y; ir.z+=a.z; ir.w+=a.w;
                    iz.x+=b.x; iz.y+=b.y; iz.z+=b.z; iz.w+=b.w;
                    in.x+=c.x; in.y+=c.y; in.z+=c.z; in.w+=c.w;
                } else {
                    hr.x+=a.x; hr.y+=a.y; hr.z+=a.z; hr.w+=a.w;
                    hz.x+=b.x; hz.y+=b.y; hz.z+=b.z; hz.w+=b.w;
                    hn.x+=c.x; hn.y+=c.y; hn.z+=c.z; hn.w+=c.w;
                }
            }
            float* hp = &g_hdec[(size_t)m * HDEC_ + j];
            float4 hv = ld4cg(hp);
            float4 o;
            { float rr = sigm(ir.x + hr.x), zz = sigm(iz.x + hz.x);
              float nn = tanhf(in.x + rr * hn.x); o.x = (1.f - zz) * nn + zz * hv.x; }
            { float rr = sigm(ir.y + hr.y), zz = sigm(iz.y + hz.y);
              float nn = tanhf(in.y + rr * hn.y); o.y = (1.f - zz) * nn + zz * hv.y; }
            { float rr = sigm(ir.z + hr.z), zz = sigm(iz.z + hz.z);
              float nn = tanhf(in.z + rr * hn.z); o.z = (1.f - zz) * nn + zz * hv.z; }
            { float rr = sigm(ir.w + hr.w), zz = sigm(iz.w + hz.w);
              float nn = tanhf(in.w + rr * hn.w); o.w = (1.f - zz) * nn + zz * hv.w; }
            st4cg(hp, o);
        }
        gridbar(gen);
        // D3: fc partials [B,512], K=640 (20 slices of 32, nchunk=1)
#pragma unroll 1
        for (int tl = bid; tl < 2 * 8 * 20; tl += nblk) {
            int s = tl % 20, r = tl / 20;
            int n0 = (r % 8) * 64, m0 = (r / 8) * 64;
            float* C = g_fcp + (size_t)s * ((size_t)B_ * FCN_);
            tile64(&sm, g_hdec, HDEC_, 0, 1, 0, fc_W, HDEC_, fc_b, s == 0, C, FCN_, 0, 0,
                   m0, n0, s * 32, 1);
        }
        gridbar(gen);
        // D4: out partials [B,128], K=512 (16 slices of 32); A = relu(sum20)
#pragma unroll 1
        for (int tl = bid; tl < 2 * 2 * 16; tl += nblk) {
            int s = tl % 16, r = tl / 16;
            int n0 = (r % 2) * 64, m0 = (r / 2) * 64;
            float* C = g_outp + (size_t)s * (B_ * D_);
            tile64(&sm, g_fcp, FCN_, (size_t)B_ * FCN_, 20, 2, out_W, FCN_, out_b, s == 0,
                   C, D_, 0, 0, m0, n0, s * 32, 1);
        }
        gridbar(gen);
    }

    // ---------- final x_mu[:, TL-1, :] ----------
    for (int i = gtid; i < B_ * D_ / 4; i += nthr) {
        int m = i / 32, d = (i % 32) * 4;
        float4 v = make_float4(0.f,0.f,0.f,0.f);
#pragma unroll
        for (int s = 0; s < 16; s++) {
            float4 u = ld4cg(&g_outp[(size_t)s * B_ * D_ + m * D_ + d]);
            v.x+=u.x; v.y+=u.y; v.z+=u.z; v.w+=u.w;
        }
        *(float4*)&x_mu[((size_t)m * TL_ + TL_ - 1) * D_ + d] = v;
    }
}

// ---------------- host launch: single graph node ---------------------------
extern "C" void kernel_launch(void* const* d_in, const int* in_sizes, int n_in,
                              void* d_out, int out_size)
{
    (void)in_sizes; (void)n_in; (void)out_size;
    const float* past    = (const float*)d_in[0];
    const float* future  = (const float*)d_in[1];
    const float* eps     = (const float*)d_in[2];
    const float* phi_Wih = (const float*)d_in[3];
    const float* phi_Whh = (const float*)d_in[4];
    const float* phi_bih = (const float*)d_in[5];
    const float* phi_bhh = (const float*)d_in[6];
    const float* xr_Wih  = (const float*)d_in[7];
    const float* xr_Whh  = (const float*)d_in[8];
    const float* xr_bih  = (const float*)d_in[9];
    const float* xr_bhh  = (const float*)d_in[10];
    const float* mu_W1   = (const float*)d_in[11];
    const float* mu_b1   = (const float*)d_in[12];
    const float* mu_W2   = (const float*)d_in[13];
    const float* mu_b2   = (const float*)d_in[14];
    const float* mu_W3   = (const float*)d_in[15];
    const float* mu_b3   = (const float*)d_in[16];
    const float* lv_W1   = (const float*)d_in[17];
    const float* lv_b1   = (const float*)d_in[18];
    const float* lv_W2   = (const float*)d_in[19];
    const float* lv_b2   = (const float*)d_in[20];
    const float* lv_W3   = (const float*)d_in[21];
    const float* lv_b3   = (const float*)d_in[22];
    const float* dec_Wih = (const float*)d_in[23];
    const float* dec_Whh = (const float*)d_in[24];
    const float* dec_bih = (const float*)d_in[25];
    const float* dec_bhh = (const float*)d_in[26];
    const float* fc_W    = (const float*)d_in[27];
    const float* fc_b    = (const float*)d_in[28];
    const float* out_W   = (const float*)d_in[29];
    const float* out_b   = (const float*)d_in[30];

    float* outp = (float*)d_out;
    float* x_mu = outp;
    float* z_mu = outp + (size_t)B_ * TL_ * D_;
    float* z_lv = z_mu + (size_t)B_ * LD_;

    int dev = 0, sms = 148;
    cudaGetDevice(&dev);
    cudaDeviceGetAttribute(&sms, cudaDevAttrMultiProcessorCount, dev);
    int nblk = sms * 4;
    if (nblk > MAXBLK) nblk = MAXBLK;

    vae_persistent<<<nblk, 128>>>(
        past, future, eps,
        phi_Wih, phi_Whh, phi_bih, phi_bhh,
        xr_Wih, xr_Whh, xr_bih, xr_bhh,
        mu_W1, mu_b1, mu_W2, mu_b2, mu_W3, mu_b3,
        lv_W1, lv_b1, lv_W2, lv_b2, lv_W3, lv_b3,
        dec_Wih, dec_Whh, dec_bih, dec_bhh,
        fc_W, fc_b, out_W, out_b,
        x_mu, z_mu, z_lv);
}

// round 14
// speedup vs baseline: 2.9159x; 1.8649x over previous
#include <cuda_runtime.h>
#include <math.h>

#define B_    128
#define PAST_ 256
#define FUT_  128
#define D_    128
#define RU_   512
#define LD_   128
#define FCN_  512
#define TL_   128
#define HDEC_ 640
#define G3RU  1536
#define G3HD  1920
#define MAXBLK 2048

// ---------------- static device scratch (no allocations anywhere) ----------
__device__ float g_gi_phi[(size_t)B_ * PAST_ * G3RU];   // 201 MB
__device__ float g_gi_xr [(size_t)B_ * FUT_  * G3RU];   // 100 MB
__device__ float g_h_phi [B_ * RU_];
__device__ float g_h_xr  [B_ * RU_];
__device__ float g_feat  [B_ * 2 * RU_];
__device__ float g_ghp   [2 * 4 * B_ * G3RU];           // enc gh partials [g][s<4]
__device__ float g_m1p   [2 * 8 * B_ * 512];
__device__ float g_m2p   [2 * 4 * B_ * 256];
__device__ float g_m3p   [2 * 2 * B_ * 128];
__device__ float g_hdec  [B_ * HDEC_];
__device__ float g_xdec  [B_ * D_];
__device__ float g_dghp  [6 * B_ * G3HD];               // dec: s=0 Gi, s=1..5 Gh splits
__device__ float g_fcp   [5 * B_ * FCN_];
__device__ float g_outp  [4 * B_ * D_];

// barrier counters: 32 keys, padded 256 B apart (spread over LTS slices).
// Monotonic across graph replays; no resets ever needed.
__device__ unsigned g_cnt_phi[32 * 64];
__device__ unsigned g_cnt_xr [32 * 64];
__device__ unsigned g_cnt_gl [32 * 64];
__device__ unsigned g_state[MAXBLK * 2];   // per-block {group gen, global gen}

// ---------------- counter-tree barrier -------------------------------------
// Arrive: one atomicAdd per block onto counter[bid&31]. Release: warp 0 polls
// the 32 counters against gen*count_k. Counters are monotonic => replay-safe.
__device__ __forceinline__ void cbar(unsigned &gen, unsigned* cnt, int mykey, int N) {
    gen++;
    __syncthreads();
    __threadfence();
    if (threadIdx.x == 0) atomicAdd(&cnt[mykey * 64], 1u);
    if (threadIdx.x < 32) {
        const unsigned target = gen * (unsigned)((N + 31 - (int)threadIdx.x) >> 5);
        unsigned delay = 32;
        bool done = *(volatile unsigned*)&cnt[threadIdx.x * 64] >= target;
        while (!__all_sync(0xffffffffu, done)) {
            __nanosleep(delay);
            if (delay < 128) delay <<= 1;
            done = *(volatile unsigned*)&cnt[threadIdx.x * 64] >= target;
        }
        __threadfence();
    }
    __syncthreads();
}

__device__ __forceinline__ float actf(float v, int act) {
    if (act == 1) return v > 0.f ? v : 0.01f * v;   // leaky_relu
    if (act == 2) return fmaxf(v, 0.f);             // relu
    return v;
}
__device__ __forceinline__ float sigm(float x) { return 1.f / (1.f + expf(-x)); }

__device__ __forceinline__ float4 ld4cg(const float* p) { return __ldcg((const float4*)p); }
__device__ __forceinline__ float4 ld4g (const float* p) { return __ldg ((const float4*)p); }
__device__ __forceinline__ void st4cg(float* p, float4 v) { __stcg((float4*)p, v); }

// ---------------- 32x64 tile GEMM, 256 threads, K-chunk = 128 --------------
// (identical to the R9 engine: register double-buffered, 2x4 per thread)
struct Smem {
    float As[32][36];
    float Ws[32][68];
};
struct Pref { float4 a, w0, w1; };

__device__ __forceinline__ Pref load_chunk(
    const float* __restrict__ A, int ldA, size_t pstride, int nred,
    const float* __restrict__ W, int ldW,
    int m0, int n0, int kb, int ar, int ac)
{
    Pref p;
    const float* ap = A + (size_t)(m0 + ar) * ldA + kb + ac;
    p.a = ld4cg(ap);
    for (int q = 1; q < nred; q++) {
        float4 u = ld4cg(ap + (size_t)q * pstride);
        p.a.x += u.x; p.a.y += u.y; p.a.z += u.z; p.a.w += u.w;
    }
    p.w0 = ld4g(W + (size_t)(n0 + ar) * ldW + kb + ac);
    p.w1 = ld4g(W + (size_t)(n0 + ar + 32) * ldW + kb + ac);
    return p;
}

__device__ __noinline__ void tile_gemm(
    Smem* sm,
    const float* __restrict__ A, int ldA, size_t pstride, int nred, int actIn,
    const float* __restrict__ W, int ldW,
    const float* __restrict__ bias, int addBias,
    float* __restrict__ C, int ldC,
    float* __restrict__ aux, int auxLd,
    int m0, int n0, int k0)
{
    const int tid = threadIdx.x;
    const int tx = tid & 15;        // 16 groups of 4 cols
    const int ty = tid >> 4;        // 16 groups of 2 rows
    const int ar = tid >> 3;        // 0..31 (A/W row)
    const int ac = (tid & 7) * 4;   // 0..28 (col)
    float acc[2][4];
#pragma unroll
    for (int i = 0; i < 2; i++)
#pragma unroll
        for (int j = 0; j < 4; j++) acc[i][j] = 0.f;

    Pref p = load_chunk(A, ldA, pstride, nred, W, ldW, m0, n0, k0, ar, ac);

#pragma unroll 1
    for (int kc = 0; kc < 4; kc++) {
        if (aux) st4cg(aux + (size_t)(m0 + ar) * auxLd + k0 + kc * 32 + ac, p.a);
        sm->As[ac + 0][ar] = actf(p.a.x, actIn);
        sm->As[ac + 1][ar] = actf(p.a.y, actIn);
        sm->As[ac + 2][ar] = actf(p.a.z, actIn);
        sm->As[ac + 3][ar] = actf(p.a.w, actIn);
        sm->Ws[ac + 0][ar] = p.w0.x;
        sm->Ws[ac + 1][ar] = p.w0.y;
        sm->Ws[ac + 2][ar] = p.w0.z;
        sm->Ws[ac + 3][ar] = p.w0.w;
        sm->Ws[ac + 0][ar + 32] = p.w1.x;
        sm->Ws[ac + 1][ar + 32] = p.w1.y;
        sm->Ws[ac + 2][ar + 32] = p.w1.z;
        sm->Ws[ac + 3][ar + 32] = p.w1.w;
        __syncthreads();
        if (kc < 3)
            p = load_chunk(A, ldA, pstride, nred, W, ldW, m0, n0, k0 + (kc + 1) * 32, ar, ac);
#pragma unroll
        for (int kk = 0; kk < 32; kk++) {
            float2 av = *(const float2*)&sm->As[kk][ty * 2];
            float4 wv = *(const float4*)&sm->Ws[kk][tx * 4];
            acc[0][0] = fmaf(av.x, wv.x, acc[0][0]);
            acc[0][1] = fmaf(av.x, wv.y, acc[0][1]);
            acc[0][2] = fmaf(av.x, wv.z, acc[0][2]);
            acc[0][3] = fmaf(av.x, wv.w, acc[0][3]);
            acc[1][0] = fmaf(av.y, wv.x, acc[1][0]);
            acc[1][1] = fmaf(av.y, wv.y, acc[1][1]);
            acc[1][2] = fmaf(av.y, wv.z, acc[1][2]);
            acc[1][3] = fmaf(av.y, wv.w, acc[1][3]);
        }
        __syncthreads();
    }

    const int n = n0 + tx * 4;
    float4 bv = addBias ? ld4g(bias + n) : make_float4(0.f, 0.f, 0.f, 0.f);
#pragma unroll
    for (int i = 0; i < 2; i++) {
        int m = m0 + ty * 2 + i;
        float4 v;
        v.x = acc[i][0] + bv.x;
        v.y = acc[i][1] + bv.y;
        v.z = acc[i][2] + bv.z;
        v.w = acc[i][3] + bv.w;
        st4cg(C + (size_t)m * ldC + n, v);
    }
}

// ---------------- persistent kernel ---------------------------------------
__global__ void __launch_bounds__(256) vae_persistent(
    const float* __restrict__ past, const float* __restrict__ future,
    const float* __restrict__ eps,
    const float* __restrict__ phi_Wih, const float* __restrict__ phi_Whh,
    const float* __restrict__ phi_bih, const float* __restrict__ phi_bhh,
    const float* __restrict__ xr_Wih,  const float* __restrict__ xr_Whh,
    const float* __restrict__ xr_bih,  const float* __restrict__ xr_bhh,
    const float* __restrict__ mu_W1, const float* __restrict__ mu_b1,
    const float* __restrict__ mu_W2, const float* __restrict__ mu_b2,
    const float* __restrict__ mu_W3, const float* __restrict__ mu_b3,
    const float* __restrict__ lv_W1, const float* __restrict__ lv_b1,
    const float* __restrict__ lv_W2, const float* __restrict__ lv_b2,
    const float* __restrict__ lv_W3, const float* __restrict__ lv_b3,
    const float* __restrict__ dec_Wih, const float* __restrict__ dec_Whh,
    const float* __restrict__ dec_bih, const float* __restrict__ dec_bhh,
    const float* __restrict__ fc_W, const float* __restrict__ fc_b,
    const float* __restrict__ out_W, const float* __restrict__ out_b,
    float* __restrict__ x_mu, float* __restrict__ z_mu_o, float* __restrict__ z_lv_o)
{
    __shared__ Smem sm;
    const int nblk = gridDim.x;
    const int bid  = blockIdx.x;
    const int tid  = threadIdx.x;
    const int gtid = bid * 256 + tid;
    const int nthr = nblk * 256;

    const int G    = nblk >> 1;                 // group size (phi | xr)
    const int grp  = (bid < G) ? 0 : 1;
    const int bidg = grp ? (bid - G) : bid;
    const int keyg = bidg & 31;
    const int keyG = bid & 31;
    unsigned* gcnt = grp ? g_cnt_xr : g_cnt_phi;

    unsigned ggen = g_state[bid * 2];
    unsigned gen2 = g_state[bid * 2 + 1];

    // ---------- P0: time-parallel input projections + zero hidden ----------
    {
        const int T1 = (B_ * PAST_ / 32) * (G3RU / 64);   // 24576
        const int T2 = (B_ * FUT_  / 32) * (G3RU / 64);   // 12288
#pragma unroll 1
        for (int tl = bid; tl < T1 + T2; tl += nblk) {
            if (tl < T1) {
                int m0 = (tl / 24) * 32, n0 = (tl % 24) * 64;
                tile_gemm(&sm, past, D_, 0, 1, 0, phi_Wih, D_, phi_bih, 1,
                          g_gi_phi, G3RU, 0, 0, m0, n0, 0);
            } else {
                int r = tl - T1;
                int m0 = (r / 24) * 32, n0 = (r % 24) * 64;
                tile_gemm(&sm, future, D_, 0, 1, 0, xr_Wih, D_, xr_bih, 1,
                          g_gi_xr, G3RU, 0, 0, m0, n0, 0);
            }
        }
        for (int i = gtid; i < 2 * B_ * RU_ / 4; i += nthr) {
            float4 z = make_float4(0.f, 0.f, 0.f, 0.f);
            if (i < B_ * RU_ / 4) st4cg(&g_h_phi[i * 4], z);
            else                  st4cg(&g_h_xr[(i - B_ * RU_ / 4) * 4], z);
        }
    }
    cbar(gen2, g_cnt_gl, keyG, nblk);

    // ---------- encoder recurrences: two independent chains ----------
    {
        const int steps = grp ? FUT_ : PAST_;
        const float* Wg  = grp ? xr_Whh : phi_Whh;
        const float* bbg = grp ? xr_bhh : phi_bhh;
        float* hg        = grp ? g_h_xr : g_h_phi;
        const int gthr = G * 256;
        const int ltid = bidg * 256 + tid;
#pragma unroll 1
        for (int t = 0; t < steps; t++) {
            // GEMM: 384 tiles (4m x 24n x 4 ksplit), 32x64 each
#pragma unroll 1
            for (int tl = bidg; tl < 384; tl += G) {
                int s = tl & 3, r = tl >> 2;
                int n0 = (r % 24) * 64, m0 = (r / 24) * 32;
                float* C = g_ghp + ((size_t)grp * 4 + s) * (B_ * G3RU);
                tile_gemm(&sm, hg, RU_, 0, 1, 0, Wg, RU_, bbg, s == 0, C, G3RU,
                          0, 0, m0, n0, s * 128);
            }
            cbar(ggen, gcnt, keyg, G);
            // GRU pointwise, float4, reduce 4 slices
            const int Q = RU_ / 4;   // 128
            for (int i = ltid; i < B_ * Q; i += gthr) {
                int m = i / Q, j = (i % Q) * 4;
                float4 sr = make_float4(0.f,0.f,0.f,0.f), sz = sr, sn = sr;
#pragma unroll
                for (int s = 0; s < 4; s++) {
                    const float* gp = g_ghp + ((size_t)grp * 4 + s) * (B_ * G3RU) + (size_t)m * G3RU;
                    float4 a = ld4cg(gp + j);
                    float4 b = ld4cg(gp + RU_ + j);
                    float4 c = ld4cg(gp + 2 * RU_ + j);
                    sr.x+=a.x; sr.y+=a.y; sr.z+=a.z; sr.w+=a.w;
                    sz.x+=b.x; sz.y+=b.y; sz.z+=b.z; sz.w+=b.w;
                    sn.x+=c.x; sn.y+=c.y; sn.z+=c.z; sn.w+=c.w;
                }
                const float* gim = grp ? (g_gi_xr  + ((size_t)m * FUT_  + t) * G3RU)
                                       : (g_gi_phi + ((size_t)m * PAST_ + t) * G3RU);
                float4 ir = ld4cg(gim + j), iz = ld4cg(gim + RU_ + j), in = ld4cg(gim + 2 * RU_ + j);
                float* hp = hg + (size_t)m * RU_ + j;
                float4 hv = ld4cg(hp);
                float4 o;
                { float rr = sigm(ir.x + sr.x), zz = sigm(iz.x + sz.x);
                  float nn = tanhf(in.x + rr * sn.x); o.x = (1.f - zz) * nn + zz * hv.x; }
                { float rr = sigm(ir.y + sr.y), zz = sigm(iz.y + sz.y);
                  float nn = tanhf(in.y + rr * sn.y); o.y = (1.f - zz) * nn + zz * hv.y; }
                { float rr = sigm(ir.z + sr.z), zz = sigm(iz.z + sz.z);
                  float nn = tanhf(in.z + rr * sn.z); o.z = (1.f - zz) * nn + zz * hv.z; }
                { float rr = sigm(ir.w + sr.w), zz = sigm(iz.w + sz.w);
                  float nn = tanhf(in.w + rr * sn.w); o.w = (1.f - zz) * nn + zz * hv.w; }
                st4cg(hp, o);
            }
            cbar(ggen, gcnt, keyg, G);
        }
    }
    cbar(gen2, g_cnt_gl, keyG, nblk);   // join: both encoders done

    // ---------- features ----------
    for (int i = gtid; i < B_ * 2 * RU_ / 4; i += nthr) {
        int m = i / (2 * RU_ / 4), c = (i % (2 * RU_ / 4)) * 4;
        float4 v = (c < RU_) ? ld4cg(&g_h_phi[m * RU_ + c]) : ld4cg(&g_h_xr[m * RU_ + c - RU_]);
        st4cg(&g_feat[m * 2 * RU_ + c], v);
    }
    cbar(gen2, g_cnt_gl, keyG, nblk);

    // ---------- MLP L1: [B,512], K=1024 (S=8) ----------
#pragma unroll 1
    for (int tl = bid; tl < 2 * 4 * 8 * 8; tl += nblk) {
        int br = tl / 256, r = tl % 256;
        int s = r & 7; r >>= 3;
        int n0 = (r % 8) * 64, m0 = (r / 8) * 32;
        const float* W = br ? lv_W1 : mu_W1;
        const float* bb = br ? lv_b1 : mu_b1;
        float* C = g_m1p + ((size_t)br * 8 + s) * (B_ * 512);
        tile_gemm(&sm, g_feat, 2 * RU_, 0, 1, 0, W, 2 * RU_, bb, s == 0, C, 512, 0, 0, m0, n0, s * 128);
    }
    cbar(gen2, g_cnt_gl, keyG, nblk);
    // ---------- MLP L2: [B,256], K=512 (S=4); A = leaky(sum8 L1) ----------
#pragma unroll 1
    for (int tl = bid; tl < 2 * 4 * 4 * 4; tl += nblk) {
        int br = tl / 64, r = tl % 64;
        int s = r & 3; r >>= 2;
        int n0 = (r % 4) * 64, m0 = (r / 4) * 32;
        const float* W = br ? lv_W2 : mu_W2;
        const float* bb = br ? lv_b2 : mu_b2;
        const float* A = g_m1p + (size_t)br * 8 * (B_ * 512);
        float* C = g_m2p + ((size_t)br * 4 + s) * (B_ * 256);
        tile_gemm(&sm, A, 512, (size_t)B_ * 512, 8, 1, W, 512, bb, s == 0, C, 256, 0, 0, m0, n0, s * 128);
    }
    cbar(gen2, g_cnt_gl, keyG, nblk);
    // ---------- MLP L3: [B,128], K=256 (S=2); A = leaky(sum4 L2) ----------
#pragma unroll 1
    for (int tl = bid; tl < 2 * 4 * 2 * 2; tl += nblk) {
        int br = tl / 16, r = tl % 16;
        int s = r & 1; r >>= 1;
        int n0 = (r % 2) * 64, m0 = (r / 2) * 32;
        const float* W = br ? lv_W3 : mu_W3;
        const float* bb = br ? lv_b3 : mu_b3;
        const float* A = g_m2p + (size_t)br * 4 * (B_ * 256);
        float* C = g_m3p + ((size_t)br * 2 + s) * (B_ * 128);
        tile_gemm(&sm, A, 256, (size_t)B_ * 256, 4, 1, W, 256, bb, s == 0, C, 128, 0, 0, m0, n0, s * 128);
    }
    cbar(gen2, g_cnt_gl, keyG, nblk);

    // ---------- prep decoder ----------
    for (int i = gtid; i < B_ * (HDEC_ + D_); i += nthr) {
        int m = i / (HDEC_ + D_), c = i % (HDEC_ + D_);
        if (c < RU_) {
            __stcg(&g_hdec[m * HDEC_ + c], __ldcg(&g_h_phi[m * RU_ + c]));
        } else if (c < HDEC_) {
            int l = c - RU_;
            float zm = __ldcg(&g_m3p[(size_t)0 * B_ * 128 + m * 128 + l])
                     + __ldcg(&g_m3p[(size_t)1 * B_ * 128 + m * 128 + l]);
            float zl = __ldcg(&g_m3p[(size_t)2 * B_ * 128 + m * 128 + l])
                     + __ldcg(&g_m3p[(size_t)3 * B_ * 128 + m * 128 + l]);
            z_mu_o[m * LD_ + l] = zm;
            z_lv_o[m * LD_ + l] = zl;
            float z = zm + __ldg(&eps[m * LD_ + l]) * expf(0.5f * zl);
            __stcg(&g_hdec[m * HDEC_ + c], z);
        } else {
            int d = c - HDEC_;
            __stcg(&g_xdec[m * D_ + d], __ldg(&past[((size_t)m * PAST_ + PAST_ - 1) * D_ + d]));
        }
    }
    cbar(gen2, g_cnt_gl, keyG, nblk);

    // ---------- decoder recurrence (4 barriers / step) ----------
#pragma unroll 1
    for (int t = 0; t < TL_; t++) {
        // D1: gate partials. s=0: Gi (K=128; A = reduce of out partials, also
        // emits x_mu[:, t-1, :] from n0==0 tiles); s=1..5: Gh K-splits.
#pragma unroll 1
        for (int tl = bid; tl < 4 * 30 * 6; tl += nblk) {
            int s = tl % 6, r = tl / 6;
            int n0 = (r % 30) * 64, m0 = (r / 30) * 32;
            float* C = g_dghp + (size_t)s * (B_ * G3HD);
            if (s == 0) {
                if (t == 0) {
                    tile_gemm(&sm, g_xdec, D_, 0, 1, 0, dec_Wih, D_, dec_bih, 1,
                              C, G3HD, 0, 0, m0, n0, 0);
                } else {
                    float* aux = (n0 == 0) ? (x_mu + (size_t)(t - 1) * D_) : 0;
                    tile_gemm(&sm, g_outp, D_, (size_t)B_ * D_, 4, 0, dec_Wih, D_, dec_bih, 1,
                              C, G3HD, aux, TL_ * D_, m0, n0, 0);
                }
            } else {
                tile_gemm(&sm, g_hdec, HDEC_, 0, 1, 0, dec_Whh, HDEC_, dec_bhh, s == 1,
                          C, G3HD, 0, 0, m0, n0, (s - 1) * 128);
            }
        }
        cbar(gen2, g_cnt_gl, keyG, nblk);
        // D2: GRU pointwise, float4
        const int Q = HDEC_ / 4;   // 160
        for (int i = gtid; i < B_ * Q; i += nthr) {
            int m = i / Q, j = (i % Q) * 4;
            const float* g0 = g_dghp + (size_t)m * G3HD;
            float4 ir = ld4cg(g0 + j), iz = ld4cg(g0 + HDEC_ + j), in = ld4cg(g0 + 2 * HDEC_ + j);
            float4 hr = make_float4(0.f,0.f,0.f,0.f), hz = hr, hn = hr;
#pragma unroll
            for (int s = 1; s < 6; s++) {
                const float* gp = g_dghp + (size_t)s * (B_ * G3HD) + (size_t)m * G3HD;
                float4 a = ld4cg(gp + j);
                float4 b = ld4cg(gp + HDEC_ + j);
                float4 c = ld4cg(gp + 2 * HDEC_ + j);
                hr.x+=a.x; hr.y+=a.y; hr.z+=a.z; hr.w+=a.w;
                hz.x+=b.x; hz.y+=b.y; hz.z+=b.z; hz.w+=b.w;
                hn.x+=c.x; hn.y+=c.y; hn.z+=c.z; hn.w+=c.w;
            }
            float* hp = &g_hdec[(size_t)m * HDEC_ + j];
            float4 hv = ld4cg(hp);
            float4 o;
            { float rr = sigm(ir.x + hr.x), zz = sigm(iz.x + hz.x);
              float nn = tanhf(in.x + rr * hn.x); o.x = (1.f - zz) * nn + zz * hv.x; }
            { float rr = sigm(ir.y + hr.y), zz = sigm(iz.y + hz.y);
              float nn = tanhf(in.y + rr * hn.y); o.y = (1.f - zz) * nn + zz * hv.y; }
            { float rr = sigm(ir.z + hr.z), zz = sigm(iz.z + hz.z);
              float nn = tanhf(in.z + rr * hn.z); o.z = (1.f - zz) * nn + zz * hv.z; }
            { float rr = sigm(ir.w + hr.w), zz = sigm(iz.w + hz.w);
              float nn = tanhf(in.w + rr * hn.w); o.w = (1.f - zz) * nn + zz * hv.w; }
            st4cg(hp, o);
        }
        cbar(gen2, g_cnt_gl, keyG, nblk);
        // D3: fc partials [B,512], K=640 (S=5)
#pragma unroll 1
        for (int tl = bid; tl < 4 * 8 * 5; tl += nblk) {
            int s = tl % 5, r = tl / 5;
            int n0 = (r % 8) * 64, m0 = (r / 8) * 32;
            float* C = g_fcp + (size_t)s * (B_ * FCN_);
            tile_gemm(&sm, g_hdec, HDEC_, 0, 1, 0, fc_W, HDEC_, fc_b, s == 0, C, FCN_, 0, 0, m0, n0, s * 128);
        }
        cbar(gen2, g_cnt_gl, keyG, nblk);
        // D4: out partials [B,128], K=512 (S=4); A = relu(sum5 fc)
#pragma unroll 1
        for (int tl = bid; tl < 4 * 2 * 4; tl += nblk) {
            int s = tl % 4, r = tl / 4;
            int n0 = (r % 2) * 64, m0 = (r / 2) * 32;
            float* C = g_outp + (size_t)s * (B_ * D_);
            tile_gemm(&sm, g_fcp, FCN_, (size_t)B_ * FCN_, 5, 2, out_W, FCN_, out_b, s == 0,
                      C, D_, 0, 0, m0, n0, s * 128);
        }
        cbar(gen2, g_cnt_gl, keyG, nblk);
    }

    // ---------- final x_mu[:, TL-1, :] ----------
    for (int i = gtid; i < B_ * D_ / 4; i += nthr) {
        int m = i / 32, d = (i % 32) * 4;
        float4 v = make_float4(0.f,0.f,0.f,0.f);
#pragma unroll
        for (int s = 0; s < 4; s++) {
            float4 u = ld4cg(&g_outp[(size_t)s * B_ * D_ + m * D_ + d]);
            v.x+=u.x; v.y+=u.y; v.z+=u.z; v.w+=u.w;
        }
        *(float4*)&x_mu[((size_t)m * TL_ + TL_ - 1) * D_ + d] = v;
    }

    // persist per-block barrier generations (monotonic across replays)
    if (tid == 0) {
        g_state[bid * 2]     = ggen;
        g_state[bid * 2 + 1] = gen2;
    }
}

// ---------------- host launch: single graph node ---------------------------
extern "C" void kernel_launch(void* const* d_in, const int* in_sizes, int n_in,
                              void* d_out, int out_size)
{
    (void)in_sizes; (void)n_in; (void)out_size;
    const float* past    = (const float*)d_in[0];
    const float* future  = (const float*)d_in[1];
    const float* eps     = (const float*)d_in[2];
    const float* phi_Wih = (const float*)d_in[3];
    const float* phi_Whh = (const float*)d_in[4];
    const float* phi_bih = (const float*)d_in[5];
    const float* phi_bhh = (const float*)d_in[6];
    const float* xr_Wih  = (const float*)d_in[7];
    const float* xr_Whh  = (const float*)d_in[8];
    const float* xr_bih  = (const float*)d_in[9];
    const float* xr_bhh  = (const float*)d_in[10];
    const float* mu_W1   = (const float*)d_in[11];
    const float* mu_b1   = (const float*)d_in[12];
    const float* mu_W2   = (const float*)d_in[13];
    const float* mu_b2   = (const float*)d_in[14];
    const float* mu_W3   = (const float*)d_in[15];
    const float* mu_b3   = (const float*)d_in[16];
    const float* lv_W1   = (const float*)d_in[17];
    const float* lv_b1   = (const float*)d_in[18];
    const float* lv_W2   = (const float*)d_in[19];
    const float* lv_b2   = (const float*)d_in[20];
    const float* lv_W3   = (const float*)d_in[21];
    const float* lv_b3   = (const float*)d_in[22];
    const float* dec_Wih = (const float*)d_in[23];
    const float* dec_Whh = (const float*)d_in[24];
    const float* dec_bih = (const float*)d_in[25];
    const float* dec_bhh = (const float*)d_in[26];
    const float* fc_W    = (const float*)d_in[27];
    const float* fc_b    = (const float*)d_in[28];
    const float* out_W   = (const float*)d_in[29];
    const float* out_b   = (const float*)d_in[30];

    float* outp = (float*)d_out;
    float* x_mu = outp;
    float* z_mu = outp + (size_t)B_ * TL_ * D_;
    float* z_lv = z_mu + (size_t)B_ * LD_;

    int dev = 0, sms = 148;
    cudaGetDevice(&dev);
    cudaDeviceGetAttribute(&sms, cudaDevAttrMultiProcessorCount, dev);
    int nblk = sms * 2;            // 2 blocks/SM of 256 threads (R9 config)
    if (nblk > MAXBLK) nblk = MAXBLK;
    nblk &= ~1;                    // even, for the 2-group split

    vae_persistent<<<nblk, 256>>>(
        past, future, eps,
        phi_Wih, phi_Whh, phi_bih, phi_bhh,
        xr_Wih, xr_Whh, xr_bih, xr_bhh,
        mu_W1, mu_b1, mu_W2, mu_b2, mu_W3, mu_b3,
        lv_W1, lv_b1, lv_W2, lv_b2, lv_W3, lv_b3,
        dec_Wih, dec_Whh, dec_bih, dec_bhh,
        fc_W, fc_b, out_W, out_b,
        x_mu, z_mu, z_lv);
}

// round 15
// speedup vs baseline: 2.9794x; 1.0218x over previous
#include <cuda_runtime.h>
#include <math.h>

#define B_    128
#define PAST_ 256
#define FUT_  128
#define D_    128
#define RU_   512
#define LD_   128
#define FCN_  512
#define TL_   128
#define HDEC_ 640
#define G3RU  1536
#define G3HD  1920
#define MAXBLK 2048

// ---------------- static device scratch (no allocations anywhere) ----------
__device__ float g_gi_phi[(size_t)B_ * PAST_ * G3RU];   // 201 MB
__device__ float g_gi_xr [(size_t)B_ * FUT_  * G3RU];   // 100 MB
__device__ float g_h_phi [B_ * RU_];
__device__ float g_h_xr  [B_ * RU_];
__device__ float g_feat  [B_ * 2 * RU_];
__device__ float g_ghp   [2 * 4 * B_ * G3RU];           // enc gh partials [g][s<4]
__device__ float g_m1p   [2 * 8 * B_ * 512];
__device__ float g_m2p   [2 * 4 * B_ * 256];
__device__ float g_m3p   [2 * 2 * B_ * 128];
__device__ float g_hdec  [B_ * HDEC_];
__device__ float g_xdec  [B_ * D_];
__device__ float g_dghp  [9 * B_ * G3HD];               // dec: s=0..3 Gi', s=4..8 Gh
__device__ float g_fcp   [5 * B_ * FCN_];
__device__ float g_M     [G3HD * FCN_];                 // dec_Wih @ out_W  [1920x512]
__device__ float g_bp    [G3HD];                        // dec_Wih @ out_b + dec_bih
__device__ float g_fc_all[(size_t)B_ * TL_ * FCN_];     // pre-relu fc, [b][t][512]
__device__ float g_xmup  [(size_t)4 * B_ * TL_ * D_];   // x_mu split-K partials

// barrier counters: 32 keys, padded 256 B apart. Monotonic across replays.
__device__ unsigned g_cnt_phi[32 * 64];
__device__ unsigned g_cnt_xr [32 * 64];
__device__ unsigned g_cnt_gl [32 * 64];
__device__ unsigned g_state[MAXBLK * 2];

// ---------------- counter-tree barrier -------------------------------------
__device__ __forceinline__ void cbar(unsigned &gen, unsigned* cnt, int mykey, int N) {
    gen++;
    __syncthreads();
    __threadfence();
    if (threadIdx.x == 0) atomicAdd(&cnt[mykey * 64], 1u);
    if (threadIdx.x < 32) {
        const unsigned target = gen * (unsigned)((N + 31 - (int)threadIdx.x) >> 5);
        unsigned delay = 32;
        bool done = *(volatile unsigned*)&cnt[threadIdx.x * 64] >= target;
        while (!__all_sync(0xffffffffu, done)) {
            __nanosleep(delay);
            if (delay < 128) delay <<= 1;
            done = *(volatile unsigned*)&cnt[threadIdx.x * 64] >= target;
        }
        __threadfence();
    }
    __syncthreads();
}

__device__ __forceinline__ float actf(float v, int act) {
    if (act == 1) return v > 0.f ? v : 0.01f * v;   // leaky_relu
    if (act == 2) return fmaxf(v, 0.f);             // relu
    return v;
}
__device__ __forceinline__ float sigm(float x) { return 1.f / (1.f + expf(-x)); }

__device__ __forceinline__ float4 ld4cg(const float* p) { return __ldcg((const float4*)p); }
__device__ __forceinline__ float4 ld4g (const float* p) { return __ldg ((const float4*)p); }
__device__ __forceinline__ void st4cg(float* p, float4 v) { __stcg((float4*)p, v); }

// ---------------- 32x64 tile GEMM, 256 threads, K-chunk = 128 --------------
struct Smem {
    float As[32][36];
    float Ws[32][68];
};
struct Pref { float4 a, w0, w1; };

__device__ __forceinline__ Pref load_chunk(
    const float* __restrict__ A, int ldA, size_t pstride, int nred,
    const float* __restrict__ W, int ldW,
    int m0, int n0, int kb, int ar, int ac)
{
    Pref p;
    const float* ap = A + (size_t)(m0 + ar) * ldA + kb + ac;
    p.a = ld4cg(ap);
    for (int q = 1; q < nred; q++) {
        float4 u = ld4cg(ap + (size_t)q * pstride);
        p.a.x += u.x; p.a.y += u.y; p.a.z += u.z; p.a.w += u.w;
    }
    p.w0 = ld4g(W + (size_t)(n0 + ar) * ldW + kb + ac);
    p.w1 = ld4g(W + (size_t)(n0 + ar + 32) * ldW + kb + ac);
    return p;
}

__device__ __noinline__ void tile_gemm(
    Smem* sm,
    const float* __restrict__ A, int ldA, size_t pstride, int nred, int actIn,
    const float* __restrict__ W, int ldW,
    const float* __restrict__ bias, int addBias,
    float* __restrict__ C, int ldC,
    float* __restrict__ aux, int auxLd,
    int m0, int n0, int k0)
{
    const int tid = threadIdx.x;
    const int tx = tid & 15;
    const int ty = tid >> 4;
    const int ar = tid >> 3;
    const int ac = (tid & 7) * 4;
    float acc[2][4];
#pragma unroll
    for (int i = 0; i < 2; i++)
#pragma unroll
        for (int j = 0; j < 4; j++) acc[i][j] = 0.f;

    Pref p = load_chunk(A, ldA, pstride, nred, W, ldW, m0, n0, k0, ar, ac);

#pragma unroll 1
    for (int kc = 0; kc < 4; kc++) {
        if (aux) st4cg(aux + (size_t)(m0 + ar) * auxLd + k0 + kc * 32 + ac, p.a);
        sm->As[ac + 0][ar] = actf(p.a.x, actIn);
        sm->As[ac + 1][ar] = actf(p.a.y, actIn);
        sm->As[ac + 2][ar] = actf(p.a.z, actIn);
        sm->As[ac + 3][ar] = actf(p.a.w, actIn);
        sm->Ws[ac + 0][ar] = p.w0.x;
        sm->Ws[ac + 1][ar] = p.w0.y;
        sm->Ws[ac + 2][ar] = p.w0.z;
        sm->Ws[ac + 3][ar] = p.w0.w;
        sm->Ws[ac + 0][ar + 32] = p.w1.x;
        sm->Ws[ac + 1][ar + 32] = p.w1.y;
        sm->Ws[ac + 2][ar + 32] = p.w1.z;
        sm->Ws[ac + 3][ar + 32] = p.w1.w;
        __syncthreads();
        if (kc < 3)
            p = load_chunk(A, ldA, pstride, nred, W, ldW, m0, n0, k0 + (kc + 1) * 32, ar, ac);
#pragma unroll
        for (int kk = 0; kk < 32; kk++) {
            float2 av = *(const float2*)&sm->As[kk][ty * 2];
            float4 wv = *(const float4*)&sm->Ws[kk][tx * 4];
            acc[0][0] = fmaf(av.x, wv.x, acc[0][0]);
            acc[0][1] = fmaf(av.x, wv.y, acc[0][1]);
            acc[0][2] = fmaf(av.x, wv.z, acc[0][2]);
            acc[0][3] = fmaf(av.x, wv.w, acc[0][3]);
            acc[1][0] = fmaf(av.y, wv.x, acc[1][0]);
            acc[1][1] = fmaf(av.y, wv.y, acc[1][1]);
            acc[1][2] = fmaf(av.y, wv.z, acc[1][2]);
            acc[1][3] = fmaf(av.y, wv.w, acc[1][3]);
        }
        __syncthreads();
    }

    const int n = n0 + tx * 4;
    float4 bv = addBias ? ld4g(bias + n) : make_float4(0.f, 0.f, 0.f, 0.f);
#pragma unroll
    for (int i = 0; i < 2; i++) {
        int m = m0 + ty * 2 + i;
        float4 v;
        v.x = acc[i][0] + bv.x;
        v.y = acc[i][1] + bv.y;
        v.z = acc[i][2] + bv.z;
        v.w = acc[i][3] + bv.w;
        st4cg(C + (size_t)m * ldC + n, v);
    }
}

// ---------------- persistent kernel ---------------------------------------
__global__ void __launch_bounds__(256, 3) vae_persistent(
    const float* __restrict__ past, const float* __restrict__ future,
    const float* __restrict__ eps,
    const float* __restrict__ phi_Wih, const float* __restrict__ phi_Whh,
    const float* __restrict__ phi_bih, const float* __restrict__ phi_bhh,
    const float* __restrict__ xr_Wih,  const float* __restrict__ xr_Whh,
    const float* __restrict__ xr_bih,  const float* __restrict__ xr_bhh,
    const float* __restrict__ mu_W1, const float* __restrict__ mu_b1,
    const float* __restrict__ mu_W2, const float* __restrict__ mu_b2,
    const float* __restrict__ mu_W3, const float* __restrict__ mu_b3,
    const float* __restrict__ lv_W1, const float* __restrict__ lv_b1,
    const float* __restrict__ lv_W2, const float* __restrict__ lv_b2,
    const float* __restrict__ lv_W3, const float* __restrict__ lv_b3,
    const float* __restrict__ dec_Wih, const float* __restrict__ dec_Whh,
    const float* __restrict__ dec_bih, const float* __restrict__ dec_bhh,
    const float* __restrict__ fc_W, const float* __restrict__ fc_b,
    const float* __restrict__ out_W, const float* __restrict__ out_b,
    float* __restrict__ x_mu, float* __restrict__ z_mu_o, float* __restrict__ z_lv_o)
{
    __shared__ Smem sm;
    const int nblk = gridDim.x;
    const int bid  = blockIdx.x;
    const int tid  = threadIdx.x;
    const int gtid = bid * 256 + tid;
    const int nthr = nblk * 256;

    const int G    = nblk >> 1;
    const int grp  = (bid < G) ? 0 : 1;
    const int bidg = grp ? (bid - G) : bid;
    const int keyg = bidg & 31;
    const int keyG = bid & 31;
    unsigned* gcnt = grp ? g_cnt_xr : g_cnt_phi;

    unsigned ggen = g_state[bid * 2];
    unsigned gen2 = g_state[bid * 2 + 1];

    // ---------- P0: input projections + zero hidden + M/b' precompute -----
    {
        const int T1 = (B_ * PAST_ / 32) * (G3RU / 64);   // 24576
        const int T2 = (B_ * FUT_  / 32) * (G3RU / 64);   // 12288
#pragma unroll 1
        for (int tl = bid; tl < T1 + T2; tl += nblk) {
            if (tl < T1) {
                int m0 = (tl / 24) * 32, n0 = (tl % 24) * 64;
                tile_gemm(&sm, past, D_, 0, 1, 0, phi_Wih, D_, phi_bih, 1,
                          g_gi_phi, G3RU, 0, 0, m0, n0, 0);
            } else {
                int r = tl - T1;
                int m0 = (r / 24) * 32, n0 = (r % 24) * 64;
                tile_gemm(&sm, future, D_, 0, 1, 0, xr_Wih, D_, xr_bih, 1,
                          g_gi_xr, G3RU, 0, 0, m0, n0, 0);
            }
        }
        for (int i = gtid; i < 2 * B_ * RU_ / 4; i += nthr) {
            float4 z = make_float4(0.f, 0.f, 0.f, 0.f);
            if (i < B_ * RU_ / 4) st4cg(&g_h_phi[i * 4], z);
            else                  st4cg(&g_h_xr[(i - B_ * RU_ / 4) * 4], z);
        }
        // M[n][f] = sum_d dec_Wih[n][d] * out_W[d][f]
        for (int i = gtid; i < G3HD * FCN_; i += nthr) {
            int n = i / FCN_, f = i % FCN_;
            float s = 0.f;
            const float* wn = dec_Wih + (size_t)n * D_;
#pragma unroll 8
            for (int d = 0; d < D_; d++) s = fmaf(wn[d], __ldg(&out_W[d * FCN_ + f]), s);
            g_M[i] = s;
        }
        // b'[n] = dec_bih[n] + sum_d dec_Wih[n][d] * out_b[d]
        for (int n = gtid; n < G3HD; n += nthr) {
            float s = __ldg(&dec_bih[n]);
            const float* wn = dec_Wih + (size_t)n * D_;
#pragma unroll 8
            for (int d = 0; d < D_; d++) s = fmaf(wn[d], __ldg(&out_b[d]), s);
            g_bp[n] = s;
        }
    }
    cbar(gen2, g_cnt_gl, keyG, nblk);

    // ---------- encoder recurrences: two independent chains ----------
    {
        const int steps = grp ? FUT_ : PAST_;
        const float* Wg  = grp ? xr_Whh : phi_Whh;
        const float* bbg = grp ? xr_bhh : phi_bhh;
        float* hg        = grp ? g_h_xr : g_h_phi;
        const int gthr = G * 256;
        const int ltid = bidg * 256 + tid;
#pragma unroll 1
        for (int t = 0; t < steps; t++) {
#pragma unroll 1
            for (int tl = bidg; tl < 384; tl += G) {
                int s = tl & 3, r = tl >> 2;
                int n0 = (r % 24) * 64, m0 = (r / 24) * 32;
                float* C = g_ghp + ((size_t)grp * 4 + s) * (B_ * G3RU);
                tile_gemm(&sm, hg, RU_, 0, 1, 0, Wg, RU_, bbg, s == 0, C, G3RU,
                          0, 0, m0, n0, s * 128);
            }
            cbar(ggen, gcnt, keyg, G);
            const int Q = RU_ / 4;   // 128
            for (int i = ltid; i < B_ * Q; i += gthr) {
                int m = i / Q, j = (i % Q) * 4;
                float4 sr = make_float4(0.f,0.f,0.f,0.f), sz = sr, sn = sr;
#pragma unroll
                for (int s = 0; s < 4; s++) {
                    const float* gp = g_ghp + ((size_t)grp * 4 + s) * (B_ * G3RU) + (size_t)m * G3RU;
                    float4 a = ld4cg(gp + j);
                    float4 b = ld4cg(gp + RU_ + j);
                    float4 c = ld4cg(gp + 2 * RU_ + j);
                    sr.x+=a.x; sr.y+=a.y; sr.z+=a.z; sr.w+=a.w;
                    sz.x+=b.x; sz.y+=b.y; sz.z+=b.z; sz.w+=b.w;
                    sn.x+=c.x; sn.y+=c.y; sn.z+=c.z; sn.w+=c.w;
                }
                const float* gim = grp ? (g_gi_xr  + ((size_t)m * FUT_  + t) * G3RU)
                                       : (g_gi_phi + ((size_t)m * PAST_ + t) * G3RU);
                float4 ir = ld4cg(gim + j), iz = ld4cg(gim + RU_ + j), in = ld4cg(gim + 2 * RU_ + j);
                float* hp = hg + (size_t)m * RU_ + j;
                float4 hv = ld4cg(hp);
                float4 o;
                { float rr = sigm(ir.x + sr.x), zz = sigm(iz.x + sz.x);
                  float nn = tanhf(in.x + rr * sn.x); o.x = (1.f - zz) * nn + zz * hv.x; }
                { float rr = sigm(ir.y + sr.y), zz = sigm(iz.y + sz.y);
                  float nn = tanhf(in.y + rr * sn.y); o.y = (1.f - zz) * nn + zz * hv.y; }
                { float rr = sigm(ir.z + sr.z), zz = sigm(iz.z + sz.z);
                  float nn = tanhf(in.z + rr * sn.z); o.z = (1.f - zz) * nn + zz * hv.z; }
                { float rr = sigm(ir.w + sr.w), zz = sigm(iz.w + sz.w);
                  float nn = tanhf(in.w + rr * sn.w); o.w = (1.f - zz) * nn + zz * hv.w; }
                st4cg(hp, o);
            }
            cbar(ggen, gcnt, keyg, G);
        }
    }
    cbar(gen2, g_cnt_gl, keyG, nblk);

    // ---------- features ----------
    for (int i = gtid; i < B_ * 2 * RU_ / 4; i += nthr) {
        int m = i / (2 * RU_ / 4), c = (i % (2 * RU_ / 4)) * 4;
        float4 v = (c < RU_) ? ld4cg(&g_h_phi[m * RU_ + c]) : ld4cg(&g_h_xr[m * RU_ + c - RU_]);
        st4cg(&g_feat[m * 2 * RU_ + c], v);
    }
    cbar(gen2, g_cnt_gl, keyG, nblk);

    // ---------- MLP L1 ----------
#pragma unroll 1
    for (int tl = bid; tl < 2 * 4 * 8 * 8; tl += nblk) {
        int br = tl / 256, r = tl % 256;
        int s = r & 7; r >>= 3;
        int n0 = (r % 8) * 64, m0 = (r / 8) * 32;
        const float* W = br ? lv_W1 : mu_W1;
        const float* bb = br ? lv_b1 : mu_b1;
        float* C = g_m1p + ((size_t)br * 8 + s) * (B_ * 512);
        tile_gemm(&sm, g_feat, 2 * RU_, 0, 1, 0, W, 2 * RU_, bb, s == 0, C, 512, 0, 0, m0, n0, s * 128);
    }
    cbar(gen2, g_cnt_gl, keyG, nblk);
    // ---------- MLP L2 ----------
#pragma unroll 1
    for (int tl = bid; tl < 2 * 4 * 4 * 4; tl += nblk) {
        int br = tl / 64, r = tl % 64;
        int s = r & 3; r >>= 2;
        int n0 = (r % 4) * 64, m0 = (r / 4) * 32;
        const float* W = br ? lv_W2 : mu_W2;
        const float* bb = br ? lv_b2 : mu_b2;
        const float* A = g_m1p + (size_t)br * 8 * (B_ * 512);
        float* C = g_m2p + ((size_t)br * 4 + s) * (B_ * 256);
        tile_gemm(&sm, A, 512, (size_t)B_ * 512, 8, 1, W, 512, bb, s == 0, C, 256, 0, 0, m0, n0, s * 128);
    }
    cbar(gen2, g_cnt_gl, keyG, nblk);
    // ---------- MLP L3 ----------
#pragma unroll 1
    for (int tl = bid; tl < 2 * 4 * 2 * 2; tl += nblk) {
        int br = tl / 16, r = tl % 16;
        int s = r & 1; r >>= 1;
        int n0 = (r % 2) * 64, m0 = (r / 2) * 32;
        const float* W = br ? lv_W3 : mu_W3;
        const float* bb = br ? lv_b3 : mu_b3;
        const float* A = g_m2p + (size_t)br * 4 * (B_ * 256);
        float* C = g_m3p + ((size_t)br * 2 + s) * (B_ * 128);
        tile_gemm(&sm, A, 256, (size_t)B_ * 256, 4, 1, W, 256, bb, s == 0, C, 128, 0, 0, m0, n0, s * 128);
    }
    cbar(gen2, g_cnt_gl, keyG, nblk);

    // ---------- prep decoder ----------
    for (int i = gtid; i < B_ * (HDEC_ + D_); i += nthr) {
        int m = i / (HDEC_ + D_), c = i % (HDEC_ + D_);
        if (c < RU_) {
            __stcg(&g_hdec[m * HDEC_ + c], __ldcg(&g_h_phi[m * RU_ + c]));
        } else if (c < HDEC_) {
            int l = c - RU_;
            float zm = __ldcg(&g_m3p[(size_t)0 * B_ * 128 + m * 128 + l])
                     + __ldcg(&g_m3p[(size_t)1 * B_ * 128 + m * 128 + l]);
            float zl = __ldcg(&g_m3p[(size_t)2 * B_ * 128 + m * 128 + l])
                     + __ldcg(&g_m3p[(size_t)3 * B_ * 128 + m * 128 + l]);
            z_mu_o[m * LD_ + l] = zm;
            z_lv_o[m * LD_ + l] = zl;
            float z = zm + __ldg(&eps[m * LD_ + l]) * expf(0.5f * zl);
            __stcg(&g_hdec[m * HDEC_ + c], z);
        } else {
            int d = c - HDEC_;
            __stcg(&g_xdec[m * D_ + d], __ldg(&past[((size_t)m * PAST_ + PAST_ - 1) * D_ + d]));
        }
    }
    cbar(gen2, g_cnt_gl, keyG, nblk);

    // ---------- decoder recurrence (3 barriers / step) ----------
    // slices: s=0..3 Gi' (K=512 from relu(fc(t-1))@M^T; t=0: s=0 only, K=128
    // from x0@Wih^T), s=4..8 Gh (K=640).
#pragma unroll 1
    for (int t = 0; t < TL_; t++) {
        const int nSlice = (t == 0) ? 6 : 9;
#pragma unroll 1
        for (int tl = bid; tl < 120 * nSlice; tl += nblk) {
            int s = tl % nSlice, r = tl / nSlice;
            int n0 = (r % 30) * 64, m0 = (r / 30) * 32;
            if (t == 0) {
                if (s == 0) {
                    tile_gemm(&sm, g_xdec, D_, 0, 1, 0, dec_Wih, D_, dec_bih, 1,
                              g_dghp + (size_t)0 * (B_ * G3HD), G3HD, 0, 0, m0, n0, 0);
                } else {
                    int sh = s - 1;
                    tile_gemm(&sm, g_hdec, HDEC_, 0, 1, 0, dec_Whh, HDEC_, dec_bhh, sh == 0,
                              g_dghp + (size_t)(4 + sh) * (B_ * G3HD), G3HD, 0, 0, m0, n0, sh * 128);
                }
            } else {
                if (s < 4) {
                    // Gi' slice s: A = relu(sum5 fc(t-1)); aux stores pre-relu fc rows
                    float* aux = (n0 == 0) ? (g_fc_all + (size_t)(t - 1) * FCN_) : 0;
                    tile_gemm(&sm, g_fcp, FCN_, (size_t)B_ * FCN_, 5, 2, g_M, FCN_, g_bp, s == 0,
                              g_dghp + (size_t)s * (B_ * G3HD), G3HD, aux, TL_ * FCN_,
                              m0, n0, s * 128);
                } else {
                    int sh = s - 4;
                    tile_gemm(&sm, g_hdec, HDEC_, 0, 1, 0, dec_Whh, HDEC_, dec_bhh, sh == 0,
                              g_dghp + (size_t)(4 + sh) * (B_ * G3HD), G3HD, 0, 0, m0, n0, sh * 128);
                }
            }
        }
        cbar(gen2, g_cnt_gl, keyG, nblk);
        // D2: GRU pointwise (Gi slices 0..ni-1, Gh slices 4..8)
        const int ni = (t == 0) ? 1 : 4;
        const int Q = HDEC_ / 4;   // 160
        for (int i = gtid; i < B_ * Q; i += nthr) {
            int m = i / Q, j = (i % Q) * 4;
            float4 ir = make_float4(0.f,0.f,0.f,0.f), iz = ir, in = ir;
            float4 hr = ir, hz = ir, hn = ir;
            for (int s = 0; s < ni; s++) {
                const float* gp = g_dghp + (size_t)s * (B_ * G3HD) + (size_t)m * G3HD;
                float4 a = ld4cg(gp + j);
                float4 b = ld4cg(gp + HDEC_ + j);
                float4 c = ld4cg(gp + 2 * HDEC_ + j);
                ir.x+=a.x; ir.y+=a.y; ir.z+=a.z; ir.w+=a.w;
                iz.x+=b.x; iz.y+=b.y; iz.z+=b.z; iz.w+=b.w;
                in.x+=c.x; in.y+=c.y; in.z+=c.z; in.w+=c.w;
            }
#pragma unroll
            for (int s = 4; s < 9; s++) {
                const float* gp = g_dghp + (size_t)s * (B_ * G3HD) + (size_t)m * G3HD;
                float4 a = ld4cg(gp + j);
                float4 b = ld4cg(gp + HDEC_ + j);
                float4 c = ld4cg(gp + 2 * HDEC_ + j);
                hr.x+=a.x; hr.y+=a.y; hr.z+=a.z; hr.w+=a.w;
                hz.x+=b.x; hz.y+=b.y; hz.z+=b.z; hz.w+=b.w;
                hn.x+=c.x; hn.y+=c.y; hn.z+=c.z; hn.w+=c.w;
            }
            float* hp = &g_hdec[(size_t)m * HDEC_ + j];
            float4 hv = ld4cg(hp);
            float4 o;
            { float rr = sigm(ir.x + hr.x), zz = sigm(iz.x + hz.x);
              float nn = tanhf(in.x + rr * hn.x); o.x = (1.f - zz) * nn + zz * hv.x; }
            { float rr = sigm(ir.y + hr.y), zz = sigm(iz.y + hz.y);
              float nn = tanhf(in.y + rr * hn.y); o.y = (1.f - zz) * nn + zz * hv.y; }
            { float rr = sigm(ir.z + hr.z), zz = sigm(iz.z + hz.z);
              float nn = tanhf(in.z + rr * hn.z); o.z = (1.f - zz) * nn + zz * hv.z; }
            { float rr = sigm(ir.w + hr.w), zz = sigm(iz.w + hz.w);
              float nn = tanhf(in.w + rr * hn.w); o.w = (1.f - zz) * nn + zz * hv.w; }
            st4cg(hp, o);
        }
        cbar(gen2, g_cnt_gl, keyG, nblk);
        // D3: fc partials [B,512], K=640 (S=5)
#pragma unroll 1
        for (int tl = bid; tl < 4 * 8 * 5; tl += nblk) {
            int s = tl % 5, r = tl / 5;
            int n0 = (r % 8) * 64, m0 = (r / 8) * 32;
            float* C = g_fcp + (size_t)s * (B_ * FCN_);
            tile_gemm(&sm, g_hdec, HDEC_, 0, 1, 0, fc_W, HDEC_, fc_b, s == 0, C, FCN_, 0, 0, m0, n0, s * 128);
        }
        cbar(gen2, g_cnt_gl, keyG, nblk);
    }

    // ---------- X1: reduce fc(TL-1) partials into g_fc_all ----------
    for (int i = gtid; i < B_ * FCN_ / 4; i += nthr) {
        int m = i / (FCN_ / 4), f = (i % (FCN_ / 4)) * 4;
        float4 v = make_float4(0.f,0.f,0.f,0.f);
#pragma unroll
        for (int s = 0; s < 5; s++) {
            float4 u = ld4cg(&g_fcp[(size_t)s * B_ * FCN_ + (size_t)m * FCN_ + f]);
            v.x+=u.x; v.y+=u.y; v.z+=u.z; v.w+=u.w;
        }
        st4cg(&g_fc_all[((size_t)m * TL_ + TL_ - 1) * FCN_ + f], v);
    }
    cbar(gen2, g_cnt_gl, keyG, nblk);

    // ---------- X2: batch x_mu GEMM: relu(fc_all) @ out_W^T, split-K 4 -----
#pragma unroll 1
    for (int tl = bid; tl < 512 * 2 * 4; tl += nblk) {
        int s = tl & 3, r = tl >> 2;
        int n0 = (r % 2) * 64, m0 = (r / 2) * 32;
        float* C = g_xmup + (size_t)s * (B_ * TL_ * D_);
        tile_gemm(&sm, g_fc_all, FCN_, 0, 1, 2, out_W, FCN_, out_b, s == 0,
                  C, D_, 0, 0, m0, n0, s * 128);
    }
    cbar(gen2, g_cnt_gl, keyG, nblk);

    // ---------- X3: reduce 4 slices -> x_mu ----------
    for (int i = gtid; i < B_ * TL_ * D_ / 4; i += nthr) {
        int d4 = i * 4;
        float4 v = make_float4(0.f,0.f,0.f,0.f);
#pragma unroll
        for (int s = 0; s < 4; s++) {
            float4 u = ld4cg(&g_xmup[(size_t)s * (B_ * TL_ * D_) + d4]);
            v.x+=u.x; v.y+=u.y; v.z+=u.z; v.w+=u.w;
        }
        *(float4*)&x_mu[d4] = v;
    }

    if (tid == 0) {
        g_state[bid * 2]     = ggen;
        g_state[bid * 2 + 1] = gen2;
    }
}

// ---------------- host launch: single graph node ---------------------------
extern "C" void kernel_launch(void* const* d_in, const int* in_sizes, int n_in,
                              void* d_out, int out_size)
{
    (void)in_sizes; (void)n_in; (void)out_size;
    const float* past    = (const float*)d_in[0];
    const float* future  = (const float*)d_in[1];
    const float* eps     = (const float*)d_in[2];
    const float* phi_Wih = (const float*)d_in[3];
    const float* phi_Whh = (const float*)d_in[4];
    const float* phi_bih = (const float*)d_in[5];
    const float* phi_bhh = (const float*)d_in[6];
    const float* xr_Wih  = (const float*)d_in[7];
    const float* xr_Whh  = (const float*)d_in[8];
    const float* xr_bih  = (const float*)d_in[9];
    const float* xr_bhh  = (const float*)d_in[10];
    const float* mu_W1   = (const float*)d_in[11];
    const float* mu_b1   = (const float*)d_in[12];
    const float* mu_W2   = (const float*)d_in[13];
    const float* mu_b2   = (const float*)d_in[14];
    const float* mu_W3   = (const float*)d_in[15];
    const float* mu_b3   = (const float*)d_in[16];
    const float* lv_W1   = (const float*)d_in[17];
    const float* lv_b1   = (const float*)d_in[18];
    const float* lv_W2   = (const float*)d_in[19];
    const float* lv_b2   = (const float*)d_in[20];
    const float* lv_W3   = (const float*)d_in[21];
    const float* lv_b3   = (const float*)d_in[22];
    const float* dec_Wih = (const float*)d_in[23];
    const float* dec_Whh = (const float*)d_in[24];
    const float* dec_bih = (const float*)d_in[25];
    const float* dec_bhh = (const float*)d_in[26];
    const float* fc_W    = (const float*)d_in[27];
    const float* fc_b    = (const float*)d_in[28];
    const float* out_W   = (const float*)d_in[29];
    const float* out_b   = (const float*)d_in[30];

    float* outp = (float*)d_out;
    float* x_mu = outp;
    float* z_mu = outp + (size_t)B_ * TL_ * D_;
    float* z_lv = z_mu + (size_t)B_ * LD_;

    int dev = 0, sms = 148;
    cudaGetDevice(&dev);
    cudaDeviceGetAttribute(&sms, cudaDevAttrMultiProcessorCount, dev);
    int nblk = sms * 3;            // 3 blocks/SM of 256 threads
    if (nblk > MAXBLK) nblk = MAXBLK;
    nblk &= ~1;                    // even, for the 2-group split

    vae_persistent<<<nblk, 256>>>(
        past, future, eps,
        phi_Wih, phi_Whh, phi_bih, phi_bhh,
        xr_Wih, xr_Whh, xr_bih, xr_bhh,
        mu_W1, mu_b1, mu_W2, mu_b2, mu_W3, mu_b3,
        lv_W1, lv_b1, lv_W2, lv_b2, lv_W3, lv_b3,
        dec_Wih, dec_Whh, dec_bih, dec_bhh,
        fc_W, fc_b, out_W, out_b,
        x_mu, z_mu, z_lv);
}